// round 5
// baseline (speedup 1.0000x reference)
#include <cuda_runtime.h>
#include <cuda_bf16.h>
#include <cstdint>

#define BATCH 4
#define SLEN  4096
#define HID   1024
#define MTOT  (BATCH * SLEN)   // 16384

// ---------------- static scratch (no runtime allocation) ----------------
__device__ __align__(16) __nv_bfloat16 g_xhi[(size_t)MTOT * HID];
__device__ __align__(16) __nv_bfloat16 g_xlo[(size_t)MTOT * HID];
__device__ __align__(16) __nv_bfloat16 g_whi[(size_t)HID * HID];
__device__ __align__(16) __nv_bfloat16 g_wlo[(size_t)HID * HID];
__device__ __align__(16) __nv_bfloat16 g_qhi[(size_t)MTOT * HID];
__device__ __align__(16) __nv_bfloat16 g_qlo[(size_t)MTOT * HID];
__device__ __align__(16) __nv_bfloat16 g_khi[(size_t)MTOT * HID];
__device__ __align__(16) __nv_bfloat16 g_klo[(size_t)MTOT * HID];
__device__ __align__(16) __nv_bfloat16 g_vhi[(size_t)MTOT * HID];
__device__ __align__(16) __nv_bfloat16 g_vlo[(size_t)MTOT * HID];
__device__ __align__(16) __nv_bfloat16 g_vthi[(size_t)MTOT * HID];   // [b][h][s]
__device__ __align__(16) __nv_bfloat16 g_vtlo[(size_t)MTOT * HID];
__device__ __align__(16) __nv_bfloat16 g_phi[(size_t)MTOT * SLEN];   // zero-padded
__device__ __align__(16) __nv_bfloat16 g_plo[(size_t)MTOT * SLEN];
__device__ __align__(16) float         g_S  [(size_t)BATCH * SLEN * SLEN];

// ---------------- engine constants ----------------
#define CHUNK_K   32
#define ASTR2     72                          // row stride in bf16 elems (64 data + 8 pad)
#define SMO_B     18432                       // 128*72*2
#define STAGE_BYTES 36864                     // A + B planes per stage
#define ENG_SMEM  (2 * STAGE_BYTES)           // 73728 -> 2 CTAs/SM

__device__ __forceinline__ uint32_t smem_u32(const void* p) {
    return (uint32_t)__cvta_generic_to_shared(p);
}

#define CP_ASYNC16(dst, src) \
    asm volatile("cp.async.cg.shared.global [%0], [%1], 16;" :: "r"(dst), "l"(src) : "memory")

#define LDMX4(R0, R1, R2, R3, addr)                                              \
    asm volatile("ldmatrix.sync.aligned.m8n8.x4.shared.b16 {%0,%1,%2,%3}, [%4];" \
                 : "=r"(R0), "=r"(R1), "=r"(R2), "=r"(R3) : "r"(addr))

#define MMA16816(C, A0, A1, A2, A3, B0, B1)                                    \
    asm volatile("mma.sync.aligned.m16n8k16.row.col.f32.bf16.bf16.f32 "        \
                 "{%0,%1,%2,%3}, {%4,%5,%6,%7}, {%8,%9}, {%0,%1,%2,%3};"       \
                 : "+f"(C[0]), "+f"(C[1]), "+f"(C[2]), "+f"(C[3])              \
                 : "r"(A0), "r"(A1), "r"(A2), "r"(A3), "r"(B0), "r"(B1))

// ---------------- stage loader: A 128x32 hi+lo, B 128x32 hi+lo ----------------
__device__ __forceinline__ void issue_stage(uint32_t st,
                                            const __nv_bfloat16* __restrict__ Ahi,
                                            const __nv_bfloat16* __restrict__ Alo,
                                            const __nv_bfloat16* __restrict__ Bhi,
                                            const __nv_bfloat16* __restrict__ Blo,
                                            int ldA, int ldB, int kc, int tid) {
    const int col0 = kc * CHUNK_K;
#pragma unroll
    for (int i = 0; i < 4; i++) {
        int id = tid + 256 * i;
        int row = id >> 3, plane = (id >> 2) & 1, quad = id & 3;
        const __nv_bfloat16* src = (plane ? Alo : Ahi) + (size_t)row * ldA + col0 + quad * 8;
        CP_ASYNC16(st + row * 144 + plane * 64 + quad * 16, src);
    }
#pragma unroll
    for (int i = 0; i < 4; i++) {
        int id = tid + 256 * i;
        int row = id >> 3, plane = (id >> 2) & 1, quad = id & 3;
        const __nv_bfloat16* src = (plane ? Blo : Bhi) + (size_t)row * ldB + col0 + quad * 8;
        CP_ASYNC16(st + SMO_B + row * 144 + plane * 64 + quad * 16, src);
    }
    asm volatile("cp.async.commit_group;" ::: "memory");
}

// ---------------- engine: acc(128x128) += 3-term hi/lo GEMM over nChunks*32 K ----------------
// 256 threads, 8 warps 2(m) x 4(n), warp tile 64x32. 2-stage double buffer,
// single barrier per chunk: buffer for kc+1 held kc-1, whose readers are past
// the barrier; load kc+1 overlaps compute kc.
__device__ __forceinline__ void gemm3(const __nv_bfloat16* __restrict__ Ahi,
                                      const __nv_bfloat16* __restrict__ Alo,
                                      const __nv_bfloat16* __restrict__ Bhi,
                                      const __nv_bfloat16* __restrict__ Blo,
                                      int ldA, int ldB, int nChunks,
                                      uint32_t sb, float (&acc)[4][4][4]) {
    const int tid  = threadIdx.x;
    const int wid  = tid >> 5;
    const int lane = tid & 31;
    const int wm   = (wid & 1) * 64;
    const int wn   = (wid >> 1) * 32;
    const int lrow = lane & 15;
    const int lkB  = (lane >> 4) * 8;

    issue_stage(sb, Ahi, Alo, Bhi, Blo, ldA, ldB, 0, tid);

    for (int kc = 0; kc < nChunks; kc++) {
        asm volatile("cp.async.wait_group 0;" ::: "memory");
        __syncthreads();

        if (kc + 1 < nChunks)
            issue_stage(sb + ((kc + 1) & 1) * STAGE_BYTES,
                        Ahi, Alo, Bhi, Blo, ldA, ldB, kc + 1, tid);

        const uint32_t sA = sb + (kc & 1) * STAGE_BYTES;
        const uint32_t sB = sA + SMO_B;

#pragma unroll
        for (int ks = 0; ks < 2; ks++) {
            uint32_t a[2][4][4];
#pragma unroll
            for (int mt = 0; mt < 4; mt++) {
                uint32_t ad = sA + ((wm + mt * 16 + lrow) * ASTR2 + ks * 16 + lkB) * 2;
                LDMX4(a[0][mt][0], a[0][mt][1], a[0][mt][2], a[0][mt][3], ad);
                LDMX4(a[1][mt][0], a[1][mt][1], a[1][mt][2], a[1][mt][3], ad + 64);
            }
            uint32_t b[2][2][4];
#pragma unroll
            for (int bg = 0; bg < 2; bg++) {
                uint32_t bd = sB + ((wn + bg * 16 + lrow) * ASTR2 + ks * 16 + lkB) * 2;
                LDMX4(b[0][bg][0], b[0][bg][1], b[0][bg][2], b[0][bg][3], bd);
                LDMX4(b[1][bg][0], b[1][bg][1], b[1][bg][2], b[1][bg][3], bd + 64);
            }
            // three product terms on the same fragments: hi.hi, hi.lo, lo.hi
#pragma unroll
            for (int t = 0; t < 3; t++) {
                const int pa = (t == 2) ? 1 : 0;
                const int pb = (t == 1) ? 1 : 0;
#pragma unroll
                for (int mt = 0; mt < 4; mt++)
#pragma unroll
                    for (int bg = 0; bg < 2; bg++) {
                        MMA16816(acc[mt][2 * bg],
                                 a[pa][mt][0], a[pa][mt][1], a[pa][mt][2], a[pa][mt][3],
                                 b[pb][bg][0], b[pb][bg][2]);
                        MMA16816(acc[mt][2 * bg + 1],
                                 a[pa][mt][0], a[pa][mt][1], a[pa][mt][2], a[pa][mt][3],
                                 b[pb][bg][1], b[pb][bg][3]);
                    }
            }
        }
    }
    __syncthreads();
}

// =================================================================================
// GEMM kernels
// =================================================================================
__global__ void __launch_bounds__(256, 2) proj_tc(int mode) {
    extern __shared__ __align__(128) char smem[];
    float acc[4][4][4];
#pragma unroll
    for (int i = 0; i < 4; i++)
#pragma unroll
        for (int j = 0; j < 4; j++)
#pragma unroll
            for (int c = 0; c < 4; c++) acc[i][j][c] = 0.0f;

    const int m0 = blockIdx.y * 128;
    const int n0 = blockIdx.x * 128;
    gemm3(g_xhi + (size_t)m0 * HID, g_xlo + (size_t)m0 * HID,
          g_whi + (size_t)n0 * HID, g_wlo + (size_t)n0 * HID,
          HID, HID, HID / CHUNK_K, smem_u32(smem), acc);

    __nv_bfloat16 *dh, *dl;
    if (mode == 0)      { dh = g_qhi; dl = g_qlo; }
    else if (mode == 1) { dh = g_khi; dl = g_klo; }
    else                { dh = g_vhi; dl = g_vlo; }

    const int tid = threadIdx.x, wid = tid >> 5, lane = tid & 31;
    const int wm = (wid & 1) * 64, wn = (wid >> 1) * 32;
    const int g = lane >> 2, t2 = (lane & 3) * 2;
#pragma unroll
    for (int mt = 0; mt < 4; mt++)
#pragma unroll
        for (int ng = 0; ng < 4; ng++)
#pragma unroll
            for (int ci = 0; ci < 4; ci++) {
                int m = m0 + wm + mt * 16 + g + ((ci >> 1) << 3);
                int n = n0 + wn + ng * 8 + t2 + (ci & 1);
                float c = acc[mt][ng][ci];
                __nv_bfloat16 hi = __float2bfloat16(c);
                __nv_bfloat16 lo = __float2bfloat16(c - __bfloat162float(hi));
                dh[(size_t)m * HID + n] = hi;
                dl[(size_t)m * HID + n] = lo;
            }
}

__global__ void __launch_bounds__(256, 2) scores_tc() {
    const int m0 = blockIdx.y * 128;
    const int n0 = blockIdx.x * 128;
    if (n0 > m0 + 127) return;                 // fully masked tile
    const int b = blockIdx.z;

    extern __shared__ __align__(128) char smem[];
    float acc[4][4][4];
#pragma unroll
    for (int i = 0; i < 4; i++)
#pragma unroll
        for (int j = 0; j < 4; j++)
#pragma unroll
            for (int c = 0; c < 4; c++) acc[i][j][c] = 0.0f;

    gemm3(g_qhi + (size_t)(b * SLEN + m0) * HID, g_qlo + (size_t)(b * SLEN + m0) * HID,
          g_khi + (size_t)(b * SLEN + n0) * HID, g_klo + (size_t)(b * SLEN + n0) * HID,
          HID, HID, HID / CHUNK_K, smem_u32(smem), acc);

    const int tid = threadIdx.x, wid = tid >> 5, lane = tid & 31;
    const int wm = (wid & 1) * 64, wn = (wid >> 1) * 32;
    const int g = lane >> 2, t2 = (lane & 3) * 2;
#pragma unroll
    for (int mt = 0; mt < 4; mt++)
#pragma unroll
        for (int ng = 0; ng < 4; ng++)
#pragma unroll
            for (int ci2 = 0; ci2 < 2; ci2++) {
                int m = m0 + wm + mt * 16 + g + ci2 * 8;
                int n = n0 + wn + ng * 8 + t2;
                float2 v = make_float2(acc[mt][ng][2 * ci2], acc[mt][ng][2 * ci2 + 1]);
                *(float2*)(g_S + ((size_t)b * SLEN + m) * SLEN + n) = v;
            }
}

__global__ void __launch_bounds__(256, 2) pv_tc(float* __restrict__ out) {
    extern __shared__ __align__(128) char smem[];
    float acc[4][4][4];
#pragma unroll
    for (int i = 0; i < 4; i++)
#pragma unroll
        for (int j = 0; j < 4; j++)
#pragma unroll
            for (int c = 0; c < 4; c++) acc[i][j][c] = 0.0f;

    const int n0 = blockIdx.x * 128;
    const int m0 = (int)(gridDim.y - 1 - blockIdx.y) * 128;   // heavy tiles first
    const int b  = blockIdx.z;
    const int nc = (m0 + 128) / CHUNK_K;

    gemm3(g_phi + (size_t)(b * SLEN + m0) * SLEN, g_plo + (size_t)(b * SLEN + m0) * SLEN,
          g_vthi + (size_t)(b * HID + n0) * SLEN, g_vtlo + (size_t)(b * HID + n0) * SLEN,
          SLEN, SLEN, nc, smem_u32(smem), acc);

    const int tid = threadIdx.x, wid = tid >> 5, lane = tid & 31;
    const int wm = (wid & 1) * 64, wn = (wid >> 1) * 32;
    const int g = lane >> 2, t2 = (lane & 3) * 2;
#pragma unroll
    for (int mt = 0; mt < 4; mt++)
#pragma unroll
        for (int ng = 0; ng < 4; ng++)
#pragma unroll
            for (int ci2 = 0; ci2 < 2; ci2++) {
                int m = m0 + wm + mt * 16 + g + ci2 * 8;
                int n = n0 + wn + ng * 8 + t2;
                float2 v = make_float2(acc[mt][ng][2 * ci2], acc[mt][ng][2 * ci2 + 1]);
                *(float2*)(out + ((size_t)b * SLEN + m) * HID + n) = v;
            }
}

// ---------------- softmax: S -> phi/plo, zero-padded to 128-tile end ----------------
__global__ void __launch_bounds__(256) softmax_kernel() {
    __shared__ float buf[SLEN];
    __shared__ float red[16];
    const int row = blockIdx.x;
    const int i   = row & (SLEN - 1);
    const int tid = threadIdx.x, wid = tid >> 5, lane = tid & 31;
    const float scale = 0.03125f;   // 1/sqrt(1024)
    const float* srow = g_S + (size_t)row * SLEN;
    const int n    = i + 1;
    const int jpad = ((i >> 7) + 1) << 7;

    float lm = -3.0e38f;
    for (int j = tid; j < n; j += 256) lm = fmaxf(lm, srow[j]);
#pragma unroll
    for (int o = 16; o; o >>= 1) lm = fmaxf(lm, __shfl_xor_sync(0xffffffffu, lm, o));
    if (lane == 0) red[wid] = lm;
    __syncthreads();
    if (tid == 0) {
        float m = red[0];
#pragma unroll
        for (int w = 1; w < 8; w++) m = fmaxf(m, red[w]);
        red[0] = m;
    }
    __syncthreads();
    const float mx = red[0];

    float ls = 0.0f;
    for (int j = tid; j < n; j += 256) {
        float e = __expf((srow[j] - mx) * scale);
        buf[j] = e;
        ls += e;
    }
#pragma unroll
    for (int o = 16; o; o >>= 1) ls += __shfl_xor_sync(0xffffffffu, ls, o);
    if (lane == 0) red[8 + wid] = ls;
    __syncthreads();
    if (tid == 0) {
        float s = 0.0f;
#pragma unroll
        for (int w = 0; w < 8; w++) s += red[8 + w];
        red[8] = 1.0f / s;
    }
    __syncthreads();
    const float inv = red[8];

    __nv_bfloat16* ph = g_phi + (size_t)row * SLEN;
    __nv_bfloat16* pl = g_plo + (size_t)row * SLEN;
    for (int j = tid; j < jpad; j += 256) {
        float p = (j < n) ? buf[j] * inv : 0.0f;
        __nv_bfloat16 hi = __float2bfloat16(p);
        __nv_bfloat16 lo = __float2bfloat16(p - __bfloat162float(hi));
        ph[j] = hi;
        pl[j] = lo;
    }
}

// ---------------- splits + V transpose ----------------
__global__ void __launch_bounds__(256) split_x(const float* __restrict__ x) {
    size_t idx = (size_t)blockIdx.x * 256 + threadIdx.x;
    float v = x[idx];
    __nv_bfloat16 hi = __float2bfloat16(v);
    __nv_bfloat16 lo = __float2bfloat16(v - __bfloat162float(hi));
    g_xhi[idx] = hi;
    g_xlo[idx] = lo;
}

__global__ void __launch_bounds__(256) split_w(const float* __restrict__ W) {
    size_t idx = (size_t)blockIdx.x * 256 + threadIdx.x;
    float v = W[idx];
    __nv_bfloat16 hi = __float2bfloat16(v);
    __nv_bfloat16 lo = __float2bfloat16(v - __bfloat162float(hi));
    g_whi[idx] = hi;
    g_wlo[idx] = lo;
}

__global__ void __launch_bounds__(256) transpose_v() {
    __shared__ __nv_bfloat16 th[32][33];
    __shared__ __nv_bfloat16 tl[32][33];
    const int b  = blockIdx.z;
    const int h0 = blockIdx.x * 32;
    const int s0 = blockIdx.y * 32;
    const int tx = threadIdx.x, ty = threadIdx.y;   // 32 x 8
    for (int r = ty; r < 32; r += 8) {
        size_t src = ((size_t)b * SLEN + s0 + r) * HID + h0 + tx;
        th[r][tx] = g_vhi[src];
        tl[r][tx] = g_vlo[src];
    }
    __syncthreads();
    for (int r = ty; r < 32; r += 8) {
        size_t dst = ((size_t)b * HID + h0 + r) * SLEN + s0 + tx;
        g_vthi[dst] = th[tx][r];
        g_vtlo[dst] = tl[tx][r];
    }
}

// =================================================================================
// Launch
// =================================================================================
extern "C" void kernel_launch(void* const* d_in, const int* in_sizes, int n_in,
                              void* d_out, int out_size) {
    (void)in_sizes; (void)n_in; (void)out_size;
    const float* x  = (const float*)d_in[0];
    const float* Wq = (const float*)d_in[1];
    const float* Wk = (const float*)d_in[2];
    const float* Wv = (const float*)d_in[3];
    float* out = (float*)d_out;

    static bool attr_set = false;
    if (!attr_set) {
        cudaFuncSetAttribute(proj_tc,   cudaFuncAttributeMaxDynamicSharedMemorySize, ENG_SMEM);
        cudaFuncSetAttribute(scores_tc, cudaFuncAttributeMaxDynamicSharedMemorySize, ENG_SMEM);
        cudaFuncSetAttribute(pv_tc,     cudaFuncAttributeMaxDynamicSharedMemorySize, ENG_SMEM);
        attr_set = true;
    }

    split_x<<<(MTOT * HID) / 256, 256>>>(x);

    dim3 pgrid(HID / 128, MTOT / 128);                 // (8, 128)
    split_w<<<(HID * HID) / 256, 256>>>(Wq);
    proj_tc<<<pgrid, 256, ENG_SMEM>>>(0);
    split_w<<<(HID * HID) / 256, 256>>>(Wk);
    proj_tc<<<pgrid, 256, ENG_SMEM>>>(1);
    split_w<<<(HID * HID) / 256, 256>>>(Wv);
    proj_tc<<<pgrid, 256, ENG_SMEM>>>(2);

    transpose_v<<<dim3(HID / 32, SLEN / 32, BATCH), dim3(32, 8)>>>();

    scores_tc<<<dim3(SLEN / 128, SLEN / 128, BATCH), 256, ENG_SMEM>>>();
    softmax_kernel<<<MTOT, 256>>>();
    pv_tc<<<dim3(HID / 128, SLEN / 128, BATCH), 256, ENG_SMEM>>>(out);
}

// round 6
// speedup vs baseline: 1.5718x; 1.5718x over previous
#include <cuda_runtime.h>
#include <cuda_bf16.h>
#include <cstdint>

#define BATCH 4
#define SLEN  4096
#define HID   1024
#define MTOT  (BATCH * SLEN)   // 16384

// ---------------- static scratch (no runtime allocation) ----------------
__device__ __align__(16) __nv_bfloat16 g_xhi[(size_t)MTOT * HID];
__device__ __align__(16) __nv_bfloat16 g_xlo[(size_t)MTOT * HID];
__device__ __align__(16) __nv_bfloat16 g_whi[(size_t)HID * HID];
__device__ __align__(16) __nv_bfloat16 g_wlo[(size_t)HID * HID];
__device__ __align__(16) __nv_bfloat16 g_qhi[(size_t)MTOT * HID];
__device__ __align__(16) __nv_bfloat16 g_qlo[(size_t)MTOT * HID];
__device__ __align__(16) __nv_bfloat16 g_khi[(size_t)MTOT * HID];
__device__ __align__(16) __nv_bfloat16 g_klo[(size_t)MTOT * HID];
__device__ __align__(16) __nv_bfloat16 g_vhi[(size_t)MTOT * HID];
__device__ __align__(16) __nv_bfloat16 g_vlo[(size_t)MTOT * HID];
__device__ __align__(16) __nv_bfloat16 g_vthi[(size_t)MTOT * HID];   // [b][h][s]
__device__ __align__(16) __nv_bfloat16 g_vtlo[(size_t)MTOT * HID];
__device__ __align__(16) __nv_bfloat16 g_phi[(size_t)MTOT * SLEN];   // zero-padded
__device__ __align__(16) __nv_bfloat16 g_plo[(size_t)MTOT * SLEN];
__device__ __align__(16) float         g_S  [(size_t)BATCH * SLEN * SLEN];

// ---------------- engine constants ----------------
#define NTHR      512
#define CHUNK_K   32
#define ASTR2     72                          // row stride in bf16 elems (64 data + 8 pad)
#define SMO_B     18432                       // 128*72*2
#define STAGE_BYTES 36864                     // A + B planes per stage
#define ENG_SMEM  (2 * STAGE_BYTES)           // 73728 -> 2 CTAs/SM

__device__ __forceinline__ uint32_t smem_u32(const void* p) {
    return (uint32_t)__cvta_generic_to_shared(p);
}

#define CP_ASYNC16(dst, src) \
    asm volatile("cp.async.cg.shared.global [%0], [%1], 16;" :: "r"(dst), "l"(src) : "memory")

#define LDMX4(R0, R1, R2, R3, addr)                                              \
    asm volatile("ldmatrix.sync.aligned.m8n8.x4.shared.b16 {%0,%1,%2,%3}, [%4];" \
                 : "=r"(R0), "=r"(R1), "=r"(R2), "=r"(R3) : "r"(addr))

#define MMA16816(C, A0, A1, A2, A3, B0, B1)                                    \
    asm volatile("mma.sync.aligned.m16n8k16.row.col.f32.bf16.bf16.f32 "        \
                 "{%0,%1,%2,%3}, {%4,%5,%6,%7}, {%8,%9}, {%0,%1,%2,%3};"       \
                 : "+f"(C[0]), "+f"(C[1]), "+f"(C[2]), "+f"(C[3])              \
                 : "r"(A0), "r"(A1), "r"(A2), "r"(A3), "r"(B0), "r"(B1))

// ---------------- stage loader: A 128x32 hi+lo, B 128x32 hi+lo (512 threads) ----------------
__device__ __forceinline__ void issue_stage(uint32_t st,
                                            const __nv_bfloat16* __restrict__ Ahi,
                                            const __nv_bfloat16* __restrict__ Alo,
                                            const __nv_bfloat16* __restrict__ Bhi,
                                            const __nv_bfloat16* __restrict__ Blo,
                                            int ldA, int ldB, int kc, int tid) {
    const int col0 = kc * CHUNK_K;
#pragma unroll
    for (int i = 0; i < 2; i++) {
        int id = tid + NTHR * i;
        int row = id >> 3, plane = (id >> 2) & 1, quad = id & 3;
        const __nv_bfloat16* src = (plane ? Alo : Ahi) + (size_t)row * ldA + col0 + quad * 8;
        CP_ASYNC16(st + row * 144 + plane * 64 + quad * 16, src);
    }
#pragma unroll
    for (int i = 0; i < 2; i++) {
        int id = tid + NTHR * i;
        int row = id >> 3, plane = (id >> 2) & 1, quad = id & 3;
        const __nv_bfloat16* src = (plane ? Blo : Bhi) + (size_t)row * ldB + col0 + quad * 8;
        CP_ASYNC16(st + SMO_B + row * 144 + plane * 64 + quad * 16, src);
    }
    asm volatile("cp.async.commit_group;" ::: "memory");
}

// ---------------- engine: acc(128x128) += 3-term hi/lo GEMM over nChunks*32 K ----------------
// 512 threads, 16 warps 4(m) x 4(n), warp tile 32x32. 2-stage double buffer,
// single barrier per chunk; load kc+1 overlaps compute kc.
__device__ __forceinline__ void gemm3(const __nv_bfloat16* __restrict__ Ahi,
                                      const __nv_bfloat16* __restrict__ Alo,
                                      const __nv_bfloat16* __restrict__ Bhi,
                                      const __nv_bfloat16* __restrict__ Blo,
                                      int ldA, int ldB, int nChunks,
                                      uint32_t sb, float (&acc)[2][4][4]) {
    const int tid  = threadIdx.x;
    const int wid  = tid >> 5;
    const int lane = tid & 31;
    const int wm   = (wid & 3) * 32;
    const int wn   = (wid >> 2) * 32;
    const int lrow = lane & 15;
    const int lkB  = (lane >> 4) * 8;

    issue_stage(sb, Ahi, Alo, Bhi, Blo, ldA, ldB, 0, tid);

    for (int kc = 0; kc < nChunks; kc++) {
        asm volatile("cp.async.wait_group 0;" ::: "memory");
        __syncthreads();

        if (kc + 1 < nChunks)
            issue_stage(sb + ((kc + 1) & 1) * STAGE_BYTES,
                        Ahi, Alo, Bhi, Blo, ldA, ldB, kc + 1, tid);

        const uint32_t sA = sb + (kc & 1) * STAGE_BYTES;
        const uint32_t sB = sA + SMO_B;

#pragma unroll
        for (int ks = 0; ks < 2; ks++) {
            uint32_t a[2][2][4];
#pragma unroll
            for (int mt = 0; mt < 2; mt++) {
                uint32_t ad = sA + ((wm + mt * 16 + lrow) * ASTR2 + ks * 16 + lkB) * 2;
                LDMX4(a[0][mt][0], a[0][mt][1], a[0][mt][2], a[0][mt][3], ad);
                LDMX4(a[1][mt][0], a[1][mt][1], a[1][mt][2], a[1][mt][3], ad + 64);
            }
            uint32_t b[2][2][4];
#pragma unroll
            for (int bg = 0; bg < 2; bg++) {
                uint32_t bd = sB + ((wn + bg * 16 + lrow) * ASTR2 + ks * 16 + lkB) * 2;
                LDMX4(b[0][bg][0], b[0][bg][1], b[0][bg][2], b[0][bg][3], bd);
                LDMX4(b[1][bg][0], b[1][bg][1], b[1][bg][2], b[1][bg][3], bd + 64);
            }
            // three product terms on the same fragments: hi.hi, hi.lo, lo.hi
#pragma unroll
            for (int t = 0; t < 3; t++) {
                const int pa = (t == 2) ? 1 : 0;
                const int pb = (t == 1) ? 1 : 0;
#pragma unroll
                for (int mt = 0; mt < 2; mt++)
#pragma unroll
                    for (int bg = 0; bg < 2; bg++) {
                        MMA16816(acc[mt][2 * bg],
                                 a[pa][mt][0], a[pa][mt][1], a[pa][mt][2], a[pa][mt][3],
                                 b[pb][bg][0], b[pb][bg][2]);
                        MMA16816(acc[mt][2 * bg + 1],
                                 a[pa][mt][0], a[pa][mt][1], a[pa][mt][2], a[pa][mt][3],
                                 b[pb][bg][1], b[pb][bg][3]);
                    }
            }
        }
    }
    __syncthreads();
}

// =================================================================================
// GEMM kernels
// =================================================================================
__global__ void __launch_bounds__(NTHR, 2) proj_tc(int mode) {
    extern __shared__ __align__(128) char smem[];
    float acc[2][4][4];
#pragma unroll
    for (int i = 0; i < 2; i++)
#pragma unroll
        for (int j = 0; j < 4; j++)
#pragma unroll
            for (int c = 0; c < 4; c++) acc[i][j][c] = 0.0f;

    const int m0 = blockIdx.y * 128;
    const int n0 = blockIdx.x * 128;
    gemm3(g_xhi + (size_t)m0 * HID, g_xlo + (size_t)m0 * HID,
          g_whi + (size_t)n0 * HID, g_wlo + (size_t)n0 * HID,
          HID, HID, HID / CHUNK_K, smem_u32(smem), acc);

    __nv_bfloat16 *dh, *dl;
    if (mode == 0)      { dh = g_qhi; dl = g_qlo; }
    else if (mode == 1) { dh = g_khi; dl = g_klo; }
    else                { dh = g_vhi; dl = g_vlo; }

    const int tid = threadIdx.x, wid = tid >> 5, lane = tid & 31;
    const int wm = (wid & 3) * 32, wn = (wid >> 2) * 32;
    const int g = lane >> 2, t2 = (lane & 3) * 2;
#pragma unroll
    for (int mt = 0; mt < 2; mt++)
#pragma unroll
        for (int ng = 0; ng < 4; ng++)
#pragma unroll
            for (int ci = 0; ci < 4; ci++) {
                int m = m0 + wm + mt * 16 + g + ((ci >> 1) << 3);
                int n = n0 + wn + ng * 8 + t2 + (ci & 1);
                float c = acc[mt][ng][ci];
                __nv_bfloat16 hi = __float2bfloat16(c);
                __nv_bfloat16 lo = __float2bfloat16(c - __bfloat162float(hi));
                dh[(size_t)m * HID + n] = hi;
                dl[(size_t)m * HID + n] = lo;
            }
}

__global__ void __launch_bounds__(NTHR, 2) scores_tc() {
    const int m0 = blockIdx.y * 128;
    const int n0 = blockIdx.x * 128;
    if (n0 > m0 + 127) return;                 // fully masked tile
    const int b = blockIdx.z;

    extern __shared__ __align__(128) char smem[];
    float acc[2][4][4];
#pragma unroll
    for (int i = 0; i < 2; i++)
#pragma unroll
        for (int j = 0; j < 4; j++)
#pragma unroll
            for (int c = 0; c < 4; c++) acc[i][j][c] = 0.0f;

    gemm3(g_qhi + (size_t)(b * SLEN + m0) * HID, g_qlo + (size_t)(b * SLEN + m0) * HID,
          g_khi + (size_t)(b * SLEN + n0) * HID, g_klo + (size_t)(b * SLEN + n0) * HID,
          HID, HID, HID / CHUNK_K, smem_u32(smem), acc);

    const int tid = threadIdx.x, wid = tid >> 5, lane = tid & 31;
    const int wm = (wid & 3) * 32, wn = (wid >> 2) * 32;
    const int g = lane >> 2, t2 = (lane & 3) * 2;
#pragma unroll
    for (int mt = 0; mt < 2; mt++)
#pragma unroll
        for (int ng = 0; ng < 4; ng++)
#pragma unroll
            for (int ci2 = 0; ci2 < 2; ci2++) {
                int m = m0 + wm + mt * 16 + g + ci2 * 8;
                int n = n0 + wn + ng * 8 + t2;
                float2 v = make_float2(acc[mt][ng][2 * ci2], acc[mt][ng][2 * ci2 + 1]);
                *(float2*)(g_S + ((size_t)b * SLEN + m) * SLEN + n) = v;
            }
}

__global__ void __launch_bounds__(NTHR, 2) pv_tc(float* __restrict__ out) {
    extern __shared__ __align__(128) char smem[];
    float acc[2][4][4];
#pragma unroll
    for (int i = 0; i < 2; i++)
#pragma unroll
        for (int j = 0; j < 4; j++)
#pragma unroll
            for (int c = 0; c < 4; c++) acc[i][j][c] = 0.0f;

    const int n0 = blockIdx.x * 128;
    const int m0 = (int)(gridDim.y - 1 - blockIdx.y) * 128;   // heavy tiles first
    const int b  = blockIdx.z;
    const int nc = (m0 + 128) / CHUNK_K;

    gemm3(g_phi + (size_t)(b * SLEN + m0) * SLEN, g_plo + (size_t)(b * SLEN + m0) * SLEN,
          g_vthi + (size_t)(b * HID + n0) * SLEN, g_vtlo + (size_t)(b * HID + n0) * SLEN,
          SLEN, SLEN, nc, smem_u32(smem), acc);

    const int tid = threadIdx.x, wid = tid >> 5, lane = tid & 31;
    const int wm = (wid & 3) * 32, wn = (wid >> 2) * 32;
    const int g = lane >> 2, t2 = (lane & 3) * 2;
#pragma unroll
    for (int mt = 0; mt < 2; mt++)
#pragma unroll
        for (int ng = 0; ng < 4; ng++)
#pragma unroll
            for (int ci2 = 0; ci2 < 2; ci2++) {
                int m = m0 + wm + mt * 16 + g + ci2 * 8;
                int n = n0 + wn + ng * 8 + t2;
                float2 v = make_float2(acc[mt][ng][2 * ci2], acc[mt][ng][2 * ci2 + 1]);
                *(float2*)(out + ((size_t)b * SLEN + m) * HID + n) = v;
            }
}

// ---------------- softmax: S -> phi/plo, zero-padded to 128-tile end ----------------
__global__ void __launch_bounds__(256) softmax_kernel() {
    __shared__ float buf[SLEN];
    __shared__ float red[16];
    const int row = blockIdx.x;
    const int i   = row & (SLEN - 1);
    const int tid = threadIdx.x, wid = tid >> 5, lane = tid & 31;
    const float scale = 0.03125f;   // 1/sqrt(1024)
    const float* srow = g_S + (size_t)row * SLEN;
    const int n    = i + 1;
    const int jpad = ((i >> 7) + 1) << 7;

    float lm = -3.0e38f;
    for (int j = tid; j < n; j += 256) lm = fmaxf(lm, srow[j]);
#pragma unroll
    for (int o = 16; o; o >>= 1) lm = fmaxf(lm, __shfl_xor_sync(0xffffffffu, lm, o));
    if (lane == 0) red[wid] = lm;
    __syncthreads();
    if (tid == 0) {
        float m = red[0];
#pragma unroll
        for (int w = 1; w < 8; w++) m = fmaxf(m, red[w]);
        red[0] = m;
    }
    __syncthreads();
    const float mx = red[0];

    float ls = 0.0f;
    for (int j = tid; j < n; j += 256) {
        float e = __expf((srow[j] - mx) * scale);
        buf[j] = e;
        ls += e;
    }
#pragma unroll
    for (int o = 16; o; o >>= 1) ls += __shfl_xor_sync(0xffffffffu, ls, o);
    if (lane == 0) red[8 + wid] = ls;
    __syncthreads();
    if (tid == 0) {
        float s = 0.0f;
#pragma unroll
        for (int w = 0; w < 8; w++) s += red[8 + w];
        red[8] = 1.0f / s;
    }
    __syncthreads();
    const float inv = red[8];

    __nv_bfloat16* ph = g_phi + (size_t)row * SLEN;
    __nv_bfloat16* pl = g_plo + (size_t)row * SLEN;
    for (int j = tid; j < jpad; j += 256) {
        float p = (j < n) ? buf[j] * inv : 0.0f;
        __nv_bfloat16 hi = __float2bfloat16(p);
        __nv_bfloat16 lo = __float2bfloat16(p - __bfloat162float(hi));
        ph[j] = hi;
        pl[j] = lo;
    }
}

// ---------------- splits + V transpose ----------------
__global__ void __launch_bounds__(256) split_x(const float* __restrict__ x) {
    size_t idx = (size_t)blockIdx.x * 256 + threadIdx.x;
    float v = x[idx];
    __nv_bfloat16 hi = __float2bfloat16(v);
    __nv_bfloat16 lo = __float2bfloat16(v - __bfloat162float(hi));
    g_xhi[idx] = hi;
    g_xlo[idx] = lo;
}

__global__ void __launch_bounds__(256) split_w(const float* __restrict__ W) {
    size_t idx = (size_t)blockIdx.x * 256 + threadIdx.x;
    float v = W[idx];
    __nv_bfloat16 hi = __float2bfloat16(v);
    __nv_bfloat16 lo = __float2bfloat16(v - __bfloat162float(hi));
    g_whi[idx] = hi;
    g_wlo[idx] = lo;
}

__global__ void __launch_bounds__(256) transpose_v() {
    __shared__ __nv_bfloat16 th[32][33];
    __shared__ __nv_bfloat16 tl[32][33];
    const int b  = blockIdx.z;
    const int h0 = blockIdx.x * 32;
    const int s0 = blockIdx.y * 32;
    const int tx = threadIdx.x, ty = threadIdx.y;   // 32 x 8
    for (int r = ty; r < 32; r += 8) {
        size_t src = ((size_t)b * SLEN + s0 + r) * HID + h0 + tx;
        th[r][tx] = g_vhi[src];
        tl[r][tx] = g_vlo[src];
    }
    __syncthreads();
    for (int r = ty; r < 32; r += 8) {
        size_t dst = ((size_t)b * HID + h0 + r) * SLEN + s0 + tx;
        g_vthi[dst] = th[tx][r];
        g_vtlo[dst] = tl[tx][r];
    }
}

// =================================================================================
// Launch
// =================================================================================
extern "C" void kernel_launch(void* const* d_in, const int* in_sizes, int n_in,
                              void* d_out, int out_size) {
    (void)in_sizes; (void)n_in; (void)out_size;
    const float* x  = (const float*)d_in[0];
    const float* Wq = (const float*)d_in[1];
    const float* Wk = (const float*)d_in[2];
    const float* Wv = (const float*)d_in[3];
    float* out = (float*)d_out;

    static bool attr_set = false;
    if (!attr_set) {
        cudaFuncSetAttribute(proj_tc,   cudaFuncAttributeMaxDynamicSharedMemorySize, ENG_SMEM);
        cudaFuncSetAttribute(scores_tc, cudaFuncAttributeMaxDynamicSharedMemorySize, ENG_SMEM);
        cudaFuncSetAttribute(pv_tc,     cudaFuncAttributeMaxDynamicSharedMemorySize, ENG_SMEM);
        attr_set = true;
    }

    split_x<<<(MTOT * HID) / 256, 256>>>(x);

    dim3 pgrid(HID / 128, MTOT / 128);                 // (8, 128)
    split_w<<<(HID * HID) / 256, 256>>>(Wq);
    proj_tc<<<pgrid, NTHR, ENG_SMEM>>>(0);
    split_w<<<(HID * HID) / 256, 256>>>(Wk);
    proj_tc<<<pgrid, NTHR, ENG_SMEM>>>(1);
    split_w<<<(HID * HID) / 256, 256>>>(Wv);
    proj_tc<<<pgrid, NTHR, ENG_SMEM>>>(2);

    transpose_v<<<dim3(HID / 32, SLEN / 32, BATCH), dim3(32, 8)>>>();

    scores_tc<<<dim3(SLEN / 128, SLEN / 128, BATCH), NTHR, ENG_SMEM>>>();
    softmax_kernel<<<MTOT, 256>>>();
    pv_tc<<<dim3(HID / 128, SLEN / 128, BATCH), NTHR, ENG_SMEM>>>(out);
}

// round 7
// speedup vs baseline: 1.9568x; 1.2449x over previous
#include <cuda_runtime.h>
#include <cuda_fp16.h>
#include <cstdint>

#define BATCH 4
#define SLEN  4096
#define HID   1024
#define MTOT  (BATCH * SLEN)   // 16384

// ---------------- static scratch (no runtime allocation) ----------------
__device__ __align__(16) __half g_xh[(size_t)MTOT * HID];
__device__ __align__(16) __half g_xl[(size_t)MTOT * HID];
__device__ __align__(16) __half g_wh[(size_t)HID * HID];
__device__ __align__(16) __half g_wl[(size_t)HID * HID];
__device__ __align__(16) __half g_qh[(size_t)MTOT * HID];   // q hi/lo (exact pair)
__device__ __align__(16) __half g_ql[(size_t)MTOT * HID];
__device__ __align__(16) __half g_kf[(size_t)MTOT * HID];   // k single fp16 plane
__device__ __align__(16) __half g_vf[(size_t)MTOT * HID];   // v single fp16 plane
__device__ __align__(16) __half g_vt[(size_t)MTOT * HID];   // v^T [b][h][s]
__device__ __align__(16) __half g_ph[(size_t)MTOT * SLEN];  // p hi/lo, zero-padded
__device__ __align__(16) __half g_pl[(size_t)MTOT * SLEN];
__device__ __align__(16) float  g_S [(size_t)BATCH * SLEN * SLEN];

// ---------------- common helpers ----------------
__device__ __forceinline__ uint32_t smem_u32(const void* p) {
    return (uint32_t)__cvta_generic_to_shared(p);
}
#define CP_ASYNC16(dst, src) \
    asm volatile("cp.async.cg.shared.global [%0], [%1], 16;" :: "r"(dst), "l"(src) : "memory")
#define LDMX4(R0, R1, R2, R3, addr)                                              \
    asm volatile("ldmatrix.sync.aligned.m8n8.x4.shared.b16 {%0,%1,%2,%3}, [%4];" \
                 : "=r"(R0), "=r"(R1), "=r"(R2), "=r"(R3) : "r"(addr))
#define MMAF16(C, A0, A1, A2, A3, B0, B1)                                      \
    asm volatile("mma.sync.aligned.m16n8k16.row.col.f32.f16.f16.f32 "          \
                 "{%0,%1,%2,%3}, {%4,%5,%6,%7}, {%8,%9}, {%0,%1,%2,%3};"       \
                 : "+f"(C[0]), "+f"(C[1]), "+f"(C[2]), "+f"(C[3])              \
                 : "r"(A0), "r"(A1), "r"(A2), "r"(A3), "r"(B0), "r"(B1))

#define CHUNK_K 32

// =================================================================================
// Engine 3 (projections): 3-term hi/lo x hi/lo. 256 thr, warps 2m x 4n (64x32),
// 3-stage pipeline. Layout: 144B rows, [hi 64B | lo 64B | 16B pad].
// =================================================================================
#define E3_SMO_B   18432
#define E3_STAGE   36864
#define E3_SMEM    (3 * E3_STAGE)   // 110592

__device__ __forceinline__ void e3_issue(uint32_t st,
                                         const __half* __restrict__ Ahi, const __half* __restrict__ Alo,
                                         const __half* __restrict__ Bhi, const __half* __restrict__ Blo,
                                         int ldA, int ldB, int kc, int tid) {
    const int col0 = kc * CHUNK_K;
#pragma unroll
    for (int i = 0; i < 4; i++) {
        int id = tid + 256 * i;
        int row = id >> 3, plane = (id >> 2) & 1, quad = id & 3;
        const __half* src = (plane ? Alo : Ahi) + (size_t)row * ldA + col0 + quad * 8;
        CP_ASYNC16(st + row * 144 + plane * 64 + quad * 16, src);
    }
#pragma unroll
    for (int i = 0; i < 4; i++) {
        int id = tid + 256 * i;
        int row = id >> 3, plane = (id >> 2) & 1, quad = id & 3;
        const __half* src = (plane ? Blo : Bhi) + (size_t)row * ldB + col0 + quad * 8;
        CP_ASYNC16(st + E3_SMO_B + row * 144 + plane * 64 + quad * 16, src);
    }
    asm volatile("cp.async.commit_group;" ::: "memory");
}

__device__ __forceinline__ void gemm3(const __half* __restrict__ Ahi, const __half* __restrict__ Alo,
                                      const __half* __restrict__ Bhi, const __half* __restrict__ Blo,
                                      int ldA, int ldB, int nChunks,
                                      uint32_t sb, float (&acc)[4][4][4]) {
    const int tid  = threadIdx.x;
    const int wid  = tid >> 5;
    const int lane = tid & 31;
    const int wm   = (wid & 1) * 64;
    const int wn   = (wid >> 1) * 32;
    const int lrow = lane & 15;
    const int lkB  = (lane >> 4) * 8;

    e3_issue(sb, Ahi, Alo, Bhi, Blo, ldA, ldB, 0, tid);
    e3_issue(sb + E3_STAGE, Ahi, Alo, Bhi, Blo, ldA, ldB, 1, tid);

    for (int kc = 0; kc < nChunks; kc++) {
        if (kc < nChunks - 1) asm volatile("cp.async.wait_group 1;" ::: "memory");
        else                  asm volatile("cp.async.wait_group 0;" ::: "memory");
        __syncthreads();

        if (kc + 2 < nChunks)
            e3_issue(sb + ((kc + 2) % 3) * E3_STAGE, Ahi, Alo, Bhi, Blo, ldA, ldB, kc + 2, tid);

        const uint32_t sA = sb + (kc % 3) * E3_STAGE;
        const uint32_t sB = sA + E3_SMO_B;
#pragma unroll
        for (int ks = 0; ks < 2; ks++) {
            uint32_t a[2][4][4];
#pragma unroll
            for (int mt = 0; mt < 4; mt++) {
                uint32_t ad = sA + ((wm + mt * 16 + lrow) * 72 + ks * 16 + lkB) * 2;
                LDMX4(a[0][mt][0], a[0][mt][1], a[0][mt][2], a[0][mt][3], ad);
                LDMX4(a[1][mt][0], a[1][mt][1], a[1][mt][2], a[1][mt][3], ad + 64);
            }
            uint32_t b[2][2][4];
#pragma unroll
            for (int bg = 0; bg < 2; bg++) {
                uint32_t bd = sB + ((wn + bg * 16 + lrow) * 72 + ks * 16 + lkB) * 2;
                LDMX4(b[0][bg][0], b[0][bg][1], b[0][bg][2], b[0][bg][3], bd);
                LDMX4(b[1][bg][0], b[1][bg][1], b[1][bg][2], b[1][bg][3], bd + 64);
            }
#pragma unroll
            for (int t = 0; t < 3; t++) {
                const int pa = (t == 2) ? 1 : 0;
                const int pb = (t == 1) ? 1 : 0;
#pragma unroll
                for (int mt = 0; mt < 4; mt++)
#pragma unroll
                    for (int bg = 0; bg < 2; bg++) {
                        MMAF16(acc[mt][2 * bg],
                               a[pa][mt][0], a[pa][mt][1], a[pa][mt][2], a[pa][mt][3],
                               b[pb][bg][0], b[pb][bg][2]);
                        MMAF16(acc[mt][2 * bg + 1],
                               a[pa][mt][0], a[pa][mt][1], a[pa][mt][2], a[pa][mt][3],
                               b[pb][bg][1], b[pb][bg][3]);
                    }
            }
        }
    }
    __syncthreads();
}

// =================================================================================
// Engine 2 (scores / PV): C = (A_hi + A_lo) . B^T, B single fp16 plane.
// 256 thr, warps 4m x 2n (warp tile 32x64), 2-stage, occ 2, no spills.
// A rows: 144B [hi|lo|pad]; B rows: 80B [64B data | 16B pad].
// =================================================================================
#define E2_SMO_B   18432                 // after A (128*144)
#define E2_STAGE   28672                 // + B 128*80
#define E2_SMEM    (2 * E2_STAGE)        // 57344 -> 2 CTAs/SM

__device__ __forceinline__ void e2_issue(uint32_t st,
                                         const __half* __restrict__ Ahi, const __half* __restrict__ Alo,
                                         const __half* __restrict__ B,
                                         int ldA, int ldB, int kc, int tid) {
    const int col0 = kc * CHUNK_K;
#pragma unroll
    for (int i = 0; i < 4; i++) {
        int id = tid + 256 * i;
        int row = id >> 3, plane = (id >> 2) & 1, quad = id & 3;
        const __half* src = (plane ? Alo : Ahi) + (size_t)row * ldA + col0 + quad * 8;
        CP_ASYNC16(st + row * 144 + plane * 64 + quad * 16, src);
    }
#pragma unroll
    for (int i = 0; i < 2; i++) {
        int id = tid + 256 * i;
        int row = id >> 2, quad = id & 3;
        const __half* src = B + (size_t)row * ldB + col0 + quad * 8;
        CP_ASYNC16(st + E2_SMO_B + row * 80 + quad * 16, src);
    }
    asm volatile("cp.async.commit_group;" ::: "memory");
}

__device__ __forceinline__ void gemm2(const __half* __restrict__ Ahi, const __half* __restrict__ Alo,
                                      const __half* __restrict__ B,
                                      int ldA, int ldB, int nChunks,
                                      uint32_t sb, float (&acc)[2][8][4]) {
    const int tid  = threadIdx.x;
    const int wid  = tid >> 5;
    const int lane = tid & 31;
    const int wm   = (wid & 3) * 32;
    const int wn   = (wid >> 2) * 64;
    const int lrow = lane & 15;
    const int lkB  = (lane >> 4) * 8;

    e2_issue(sb, Ahi, Alo, B, ldA, ldB, 0, tid);

    for (int kc = 0; kc < nChunks; kc++) {
        asm volatile("cp.async.wait_group 0;" ::: "memory");
        __syncthreads();

        if (kc + 1 < nChunks)
            e2_issue(sb + ((kc + 1) & 1) * E2_STAGE, Ahi, Alo, B, ldA, ldB, kc + 1, tid);

        const uint32_t sA = sb + (kc & 1) * E2_STAGE;
        const uint32_t sB = sA + E2_SMO_B;
#pragma unroll
        for (int ks = 0; ks < 2; ks++) {
            uint32_t a[2][2][4];
#pragma unroll
            for (int mt = 0; mt < 2; mt++) {
                uint32_t ad = sA + ((wm + mt * 16 + lrow) * 72 + ks * 16 + lkB) * 2;
                LDMX4(a[0][mt][0], a[0][mt][1], a[0][mt][2], a[0][mt][3], ad);
                LDMX4(a[1][mt][0], a[1][mt][1], a[1][mt][2], a[1][mt][3], ad + 64);
            }
            uint32_t b[4][4];
#pragma unroll
            for (int g = 0; g < 4; g++) {
                uint32_t bd = sB + (wn + g * 16 + lrow) * 80 + (ks * 16 + lkB) * 2;
                LDMX4(b[g][0], b[g][1], b[g][2], b[g][3], bd);
            }
#pragma unroll
            for (int pa = 0; pa < 2; pa++)
#pragma unroll
                for (int mt = 0; mt < 2; mt++)
#pragma unroll
                    for (int g = 0; g < 4; g++) {
                        MMAF16(acc[mt][2 * g],
                               a[pa][mt][0], a[pa][mt][1], a[pa][mt][2], a[pa][mt][3],
                               b[g][0], b[g][2]);
                        MMAF16(acc[mt][2 * g + 1],
                               a[pa][mt][0], a[pa][mt][1], a[pa][mt][2], a[pa][mt][3],
                               b[g][1], b[g][3]);
                    }
        }
    }
    __syncthreads();
}

// =================================================================================
// Kernels
// =================================================================================
__global__ void __launch_bounds__(256) proj_tc(int mode) {
    extern __shared__ __align__(128) char smem[];
    float acc[4][4][4];
#pragma unroll
    for (int i = 0; i < 4; i++)
#pragma unroll
        for (int j = 0; j < 4; j++)
#pragma unroll
            for (int c = 0; c < 4; c++) acc[i][j][c] = 0.0f;

    const int m0 = blockIdx.y * 128;
    const int n0 = blockIdx.x * 128;
    gemm3(g_xh + (size_t)m0 * HID, g_xl + (size_t)m0 * HID,
          g_wh + (size_t)n0 * HID, g_wl + (size_t)n0 * HID,
          HID, HID, HID / CHUNK_K, smem_u32(smem), acc);

    const int tid = threadIdx.x, wid = tid >> 5, lane = tid & 31;
    const int wm = (wid & 1) * 64, wn = (wid >> 1) * 32;
    const int g = lane >> 2, t2 = (lane & 3) * 2;
#pragma unroll
    for (int mt = 0; mt < 4; mt++)
#pragma unroll
        for (int ng = 0; ng < 4; ng++)
#pragma unroll
            for (int ci = 0; ci < 4; ci++) {
                int m = m0 + wm + mt * 16 + g + ((ci >> 1) << 3);
                int n = n0 + wn + ng * 8 + t2 + (ci & 1);
                float c = acc[mt][ng][ci];
                size_t off = (size_t)m * HID + n;
                if (mode == 0) {
                    __half hi = __float2half_rn(c);
                    g_qh[off] = hi;
                    g_ql[off] = __float2half_rn(c - __half2float(hi));
                } else if (mode == 1) {
                    g_kf[off] = __float2half_rn(c);
                } else {
                    g_vf[off] = __float2half_rn(c);
                }
            }
}

__global__ void __launch_bounds__(256, 2) scores_tc() {
    const int m0 = blockIdx.y * 128;
    const int n0 = blockIdx.x * 128;
    if (n0 > m0 + 127) return;                 // fully masked tile
    const int b = blockIdx.z;

    extern __shared__ __align__(128) char smem[];
    float acc[2][8][4];
#pragma unroll
    for (int i = 0; i < 2; i++)
#pragma unroll
        for (int j = 0; j < 8; j++)
#pragma unroll
            for (int c = 0; c < 4; c++) acc[i][j][c] = 0.0f;

    gemm2(g_qh + (size_t)(b * SLEN + m0) * HID, g_ql + (size_t)(b * SLEN + m0) * HID,
          g_kf + (size_t)(b * SLEN + n0) * HID,
          HID, HID, HID / CHUNK_K, smem_u32(smem), acc);

    const int tid = threadIdx.x, wid = tid >> 5, lane = tid & 31;
    const int wm = (wid & 3) * 32, wn = (wid >> 2) * 64;
    const int g = lane >> 2, t2 = (lane & 3) * 2;
#pragma unroll
    for (int mt = 0; mt < 2; mt++)
#pragma unroll
        for (int ng = 0; ng < 8; ng++)
#pragma unroll
            for (int ci2 = 0; ci2 < 2; ci2++) {
                int m = m0 + wm + mt * 16 + g + ci2 * 8;
                int n = n0 + wn + ng * 8 + t2;
                float2 v = make_float2(acc[mt][ng][2 * ci2], acc[mt][ng][2 * ci2 + 1]);
                *(float2*)(g_S + ((size_t)b * SLEN + m) * SLEN + n) = v;
            }
}

__global__ void __launch_bounds__(256, 2) pv_tc(float* __restrict__ out) {
    extern __shared__ __align__(128) char smem[];
    float acc[2][8][4];
#pragma unroll
    for (int i = 0; i < 2; i++)
#pragma unroll
        for (int j = 0; j < 8; j++)
#pragma unroll
            for (int c = 0; c < 4; c++) acc[i][j][c] = 0.0f;

    const int n0 = blockIdx.x * 128;
    const int m0 = (int)(gridDim.y - 1 - blockIdx.y) * 128;   // heavy tiles first
    const int b  = blockIdx.z;
    const int nc = (m0 + 128) / CHUNK_K;

    gemm2(g_ph + (size_t)(b * SLEN + m0) * SLEN, g_pl + (size_t)(b * SLEN + m0) * SLEN,
          g_vt + (size_t)(b * HID + n0) * SLEN,
          SLEN, SLEN, nc, smem_u32(smem), acc);

    const int tid = threadIdx.x, wid = tid >> 5, lane = tid & 31;
    const int wm = (wid & 3) * 32, wn = (wid >> 2) * 64;
    const int g = lane >> 2, t2 = (lane & 3) * 2;
#pragma unroll
    for (int mt = 0; mt < 2; mt++)
#pragma unroll
        for (int ng = 0; ng < 8; ng++)
#pragma unroll
            for (int ci2 = 0; ci2 < 2; ci2++) {
                int m = m0 + wm + mt * 16 + g + ci2 * 8;
                int n = n0 + wn + ng * 8 + t2;
                float2 v = make_float2(acc[mt][ng][2 * ci2], acc[mt][ng][2 * ci2 + 1]);
                *(float2*)(out + ((size_t)b * SLEN + m) * HID + n) = v;
            }
}

// ---------------- softmax: S -> p hi/lo fp16, zero-padded to 128-tile end ----------------
__global__ void __launch_bounds__(256) softmax_kernel() {
    __shared__ float buf[SLEN];
    __shared__ float red[16];
    const int row = blockIdx.x;
    const int i   = row & (SLEN - 1);
    const int tid = threadIdx.x, wid = tid >> 5, lane = tid & 31;
    const float scale = 0.03125f;   // 1/sqrt(1024)
    const float* srow = g_S + (size_t)row * SLEN;
    const int n    = i + 1;
    const int jpad = ((i >> 7) + 1) << 7;

    float lm = -3.0e38f;
    for (int j = tid; j < n; j += 256) lm = fmaxf(lm, srow[j]);
#pragma unroll
    for (int o = 16; o; o >>= 1) lm = fmaxf(lm, __shfl_xor_sync(0xffffffffu, lm, o));
    if (lane == 0) red[wid] = lm;
    __syncthreads();
    if (tid == 0) {
        float m = red[0];
#pragma unroll
        for (int w = 1; w < 8; w++) m = fmaxf(m, red[w]);
        red[0] = m;
    }
    __syncthreads();
    const float mx = red[0];

    float ls = 0.0f;
    for (int j = tid; j < n; j += 256) {
        float e = __expf((srow[j] - mx) * scale);
        buf[j] = e;
        ls += e;
    }
#pragma unroll
    for (int o = 16; o; o >>= 1) ls += __shfl_xor_sync(0xffffffffu, ls, o);
    if (lane == 0) red[8 + wid] = ls;
    __syncthreads();
    if (tid == 0) {
        float s = 0.0f;
#pragma unroll
        for (int w = 0; w < 8; w++) s += red[8 + w];
        red[8] = 1.0f / s;
    }
    __syncthreads();
    const float inv = red[8];

    __half* ph = g_ph + (size_t)row * SLEN;
    __half* pl = g_pl + (size_t)row * SLEN;
    for (int j = tid; j < jpad; j += 256) {
        float p = (j < n) ? buf[j] * inv : 0.0f;
        __half hi = __float2half_rn(p);
        ph[j] = hi;
        pl[j] = __float2half_rn(p - __half2float(hi));
    }
}

// ---------------- splits + V transpose ----------------
__global__ void __launch_bounds__(256) split_x(const float* __restrict__ x) {
    size_t idx = (size_t)blockIdx.x * 256 + threadIdx.x;
    float v = x[idx];
    __half hi = __float2half_rn(v);
    g_xh[idx] = hi;
    g_xl[idx] = __float2half_rn(v - __half2float(hi));
}

__global__ void __launch_bounds__(256) split_w(const float* __restrict__ W) {
    size_t idx = (size_t)blockIdx.x * 256 + threadIdx.x;
    float v = W[idx];
    __half hi = __float2half_rn(v);
    g_wh[idx] = hi;
    g_wl[idx] = __float2half_rn(v - __half2float(hi));
}

__global__ void __launch_bounds__(256) transpose_v() {
    __shared__ __half tv[32][33];
    const int b  = blockIdx.z;
    const int h0 = blockIdx.x * 32;
    const int s0 = blockIdx.y * 32;
    const int tx = threadIdx.x, ty = threadIdx.y;   // 32 x 8
    for (int r = ty; r < 32; r += 8)
        tv[r][tx] = g_vf[((size_t)b * SLEN + s0 + r) * HID + h0 + tx];
    __syncthreads();
    for (int r = ty; r < 32; r += 8)
        g_vt[((size_t)b * HID + h0 + r) * SLEN + s0 + tx] = tv[tx][r];
}

// =================================================================================
// Launch (ordered so scores_tc is launch index 5 for ncu -s 5 -c 1)
// =================================================================================
extern "C" void kernel_launch(void* const* d_in, const int* in_sizes, int n_in,
                              void* d_out, int out_size) {
    (void)in_sizes; (void)n_in; (void)out_size;
    const float* x  = (const float*)d_in[0];
    const float* Wq = (const float*)d_in[1];
    const float* Wk = (const float*)d_in[2];
    const float* Wv = (const float*)d_in[3];
    float* out = (float*)d_out;

    static bool attr_set = false;
    if (!attr_set) {
        cudaFuncSetAttribute(proj_tc,   cudaFuncAttributeMaxDynamicSharedMemorySize, E3_SMEM);
        cudaFuncSetAttribute(scores_tc, cudaFuncAttributeMaxDynamicSharedMemorySize, E2_SMEM);
        cudaFuncSetAttribute(pv_tc,     cudaFuncAttributeMaxDynamicSharedMemorySize, E2_SMEM);
        attr_set = true;
    }

    dim3 pgrid(HID / 128, MTOT / 128);                 // (8, 128)

    split_x<<<(MTOT * HID) / 256, 256>>>(x);           // launch 0
    split_w<<<(HID * HID) / 256, 256>>>(Wq);           // 1
    proj_tc<<<pgrid, 256, E3_SMEM>>>(0);               // 2  -> q
    split_w<<<(HID * HID) / 256, 256>>>(Wk);           // 3
    proj_tc<<<pgrid, 256, E3_SMEM>>>(1);               // 4  -> k
    scores_tc<<<dim3(SLEN / 128, SLEN / 128, BATCH), 256, E2_SMEM>>>();   // 5 (profiled)
    split_w<<<(HID * HID) / 256, 256>>>(Wv);           // 6
    proj_tc<<<pgrid, 256, E3_SMEM>>>(2);               // 7  -> v
    transpose_v<<<dim3(HID / 32, SLEN / 32, BATCH), dim3(32, 8)>>>();     // 8
    softmax_kernel<<<MTOT, 256>>>();                   // 9
    pv_tc<<<dim3(HID / 128, SLEN / 128, BATCH), 256, E2_SMEM>>>(out);     // 10
}

// round 8
// speedup vs baseline: 2.2814x; 1.1659x over previous
#include <cuda_runtime.h>
#include <cuda_fp16.h>
#include <cstdint>

#define BATCH 4
#define SLEN  4096
#define HID   1024
#define MTOT  (BATCH * SLEN)   // 16384

// ---------------- static scratch (no runtime allocation) ----------------
__device__ __align__(16) __half g_xh[(size_t)MTOT * HID];
__device__ __align__(16) __half g_xl[(size_t)MTOT * HID];
__device__ __align__(16) __half g_wf[3][(size_t)HID * HID];  // Wq,Wk,Wv single fp16 planes
__device__ __align__(16) __half g_qh[(size_t)MTOT * HID];    // q hi/lo (exact pair)
__device__ __align__(16) __half g_ql[(size_t)MTOT * HID];
__device__ __align__(16) __half g_kf[(size_t)MTOT * HID];    // k single fp16 plane
__device__ __align__(16) __half g_vf[(size_t)MTOT * HID];    // v single fp16 plane
__device__ __align__(16) __half g_vt[(size_t)MTOT * HID];    // v^T [b][h][s]
__device__ __align__(16) __half g_ph[(size_t)MTOT * SLEN];   // p hi/lo, zero-padded
__device__ __align__(16) __half g_pl[(size_t)MTOT * SLEN];
__device__ __align__(16) float  g_S [(size_t)BATCH * SLEN * SLEN];

// ---------------- common helpers ----------------
__device__ __forceinline__ uint32_t smem_u32(const void* p) {
    return (uint32_t)__cvta_generic_to_shared(p);
}
#define CP_ASYNC16(dst, src) \
    asm volatile("cp.async.cg.shared.global [%0], [%1], 16;" :: "r"(dst), "l"(src) : "memory")
#define LDMX4(R0, R1, R2, R3, addr)                                              \
    asm volatile("ldmatrix.sync.aligned.m8n8.x4.shared.b16 {%0,%1,%2,%3}, [%4];" \
                 : "=r"(R0), "=r"(R1), "=r"(R2), "=r"(R3) : "r"(addr))
#define MMAF16(C, A0, A1, A2, A3, B0, B1)                                      \
    asm volatile("mma.sync.aligned.m16n8k16.row.col.f32.f16.f16.f32 "          \
                 "{%0,%1,%2,%3}, {%4,%5,%6,%7}, {%8,%9}, {%0,%1,%2,%3};"       \
                 : "+f"(C[0]), "+f"(C[1]), "+f"(C[2]), "+f"(C[3])              \
                 : "r"(A0), "r"(A1), "r"(A2), "r"(A3), "r"(B0), "r"(B1))

#define CHUNK_K 32

// =================================================================================
// Engine 2 (all GEMMs): C = (A_hi + A_lo) . B^T, B single fp16 plane.
// 256 thr, warps 4m x 2n (warp tile 32x64), 2-stage, occ 2.
// A rows: 144B [hi 64B | lo 64B | 16B pad]; B rows: 80B [64B data | 16B pad].
// =================================================================================
#define E2_SMO_B   18432                 // after A (128*144)
#define E2_STAGE   28672                 // + B 128*80
#define E2_SMEM    (2 * E2_STAGE)        // 57344 -> 2 CTAs/SM

__device__ __forceinline__ void e2_issue(uint32_t st,
                                         const __half* __restrict__ Ahi, const __half* __restrict__ Alo,
                                         const __half* __restrict__ B,
                                         int ldA, int ldB, int kc, int tid) {
    const int col0 = kc * CHUNK_K;
#pragma unroll
    for (int i = 0; i < 4; i++) {
        int id = tid + 256 * i;
        int row = id >> 3, plane = (id >> 2) & 1, quad = id & 3;
        const __half* src = (plane ? Alo : Ahi) + (size_t)row * ldA + col0 + quad * 8;
        CP_ASYNC16(st + row * 144 + plane * 64 + quad * 16, src);
    }
#pragma unroll
    for (int i = 0; i < 2; i++) {
        int id = tid + 256 * i;
        int row = id >> 2, quad = id & 3;
        const __half* src = B + (size_t)row * ldB + col0 + quad * 8;
        CP_ASYNC16(st + E2_SMO_B + row * 80 + quad * 16, src);
    }
    asm volatile("cp.async.commit_group;" ::: "memory");
}

__device__ __forceinline__ void gemm2(const __half* __restrict__ Ahi, const __half* __restrict__ Alo,
                                      const __half* __restrict__ B,
                                      int ldA, int ldB, int nChunks,
                                      uint32_t sb, float (&acc)[2][8][4]) {
    const int tid  = threadIdx.x;
    const int wid  = tid >> 5;
    const int lane = tid & 31;
    const int wm   = (wid & 3) * 32;
    const int wn   = (wid >> 2) * 64;
    const int lrow = lane & 15;
    const int lkB  = (lane >> 4) * 8;

    e2_issue(sb, Ahi, Alo, B, ldA, ldB, 0, tid);

    for (int kc = 0; kc < nChunks; kc++) {
        asm volatile("cp.async.wait_group 0;" ::: "memory");
        __syncthreads();

        if (kc + 1 < nChunks)
            e2_issue(sb + ((kc + 1) & 1) * E2_STAGE, Ahi, Alo, B, ldA, ldB, kc + 1, tid);

        const uint32_t sA = sb + (kc & 1) * E2_STAGE;
        const uint32_t sB = sA + E2_SMO_B;
#pragma unroll
        for (int ks = 0; ks < 2; ks++) {
            uint32_t a[2][2][4];
#pragma unroll
            for (int mt = 0; mt < 2; mt++) {
                uint32_t ad = sA + ((wm + mt * 16 + lrow) * 72 + ks * 16 + lkB) * 2;
                LDMX4(a[0][mt][0], a[0][mt][1], a[0][mt][2], a[0][mt][3], ad);
                LDMX4(a[1][mt][0], a[1][mt][1], a[1][mt][2], a[1][mt][3], ad + 64);
            }
            uint32_t b[4][4];
#pragma unroll
            for (int g = 0; g < 4; g++) {
                uint32_t bd = sB + (wn + g * 16 + lrow) * 80 + (ks * 16 + lkB) * 2;
                LDMX4(b[g][0], b[g][1], b[g][2], b[g][3], bd);
            }
#pragma unroll
            for (int pa = 0; pa < 2; pa++)
#pragma unroll
                for (int mt = 0; mt < 2; mt++)
#pragma unroll
                    for (int g = 0; g < 4; g++) {
                        MMAF16(acc[mt][2 * g],
                               a[pa][mt][0], a[pa][mt][1], a[pa][mt][2], a[pa][mt][3],
                               b[g][0], b[g][2]);
                        MMAF16(acc[mt][2 * g + 1],
                               a[pa][mt][0], a[pa][mt][1], a[pa][mt][2], a[pa][mt][3],
                               b[g][1], b[g][3]);
                    }
        }
    }
    __syncthreads();
}

// =================================================================================
// GEMM kernels
// =================================================================================
__global__ void __launch_bounds__(256, 2) proj_tc(int mode) {
    extern __shared__ __align__(128) char smem[];
    float acc[2][8][4];
#pragma unroll
    for (int i = 0; i < 2; i++)
#pragma unroll
        for (int j = 0; j < 8; j++)
#pragma unroll
            for (int c = 0; c < 4; c++) acc[i][j][c] = 0.0f;

    const int m0 = blockIdx.y * 128;
    const int n0 = blockIdx.x * 128;
    gemm2(g_xh + (size_t)m0 * HID, g_xl + (size_t)m0 * HID,
          g_wf[mode] + (size_t)n0 * HID,
          HID, HID, HID / CHUNK_K, smem_u32(smem), acc);

    const int tid = threadIdx.x, wid = tid >> 5, lane = tid & 31;
    const int wm = (wid & 3) * 32, wn = (wid >> 2) * 64;
    const int g = lane >> 2, t2 = (lane & 3) * 2;
#pragma unroll
    for (int mt = 0; mt < 2; mt++)
#pragma unroll
        for (int ng = 0; ng < 8; ng++)
#pragma unroll
            for (int ci = 0; ci < 4; ci++) {
                int m = m0 + wm + mt * 16 + g + ((ci >> 1) << 3);
                int n = n0 + wn + ng * 8 + t2 + (ci & 1);
                float c = acc[mt][ng][ci];
                size_t off = (size_t)m * HID + n;
                if (mode == 0) {
                    __half hi = __float2half_rn(c);
                    g_qh[off] = hi;
                    g_ql[off] = __float2half_rn(c - __half2float(hi));
                } else if (mode == 1) {
                    g_kf[off] = __float2half_rn(c);
                } else {
                    g_vf[off] = __float2half_rn(c);
                }
            }
}

__global__ void __launch_bounds__(256, 2) scores_tc() {
    const int m0 = blockIdx.y * 128;
    const int n0 = blockIdx.x * 128;
    if (n0 > m0 + 127) return;                 // fully masked tile
    const int b = blockIdx.z;

    extern __shared__ __align__(128) char smem[];
    float acc[2][8][4];
#pragma unroll
    for (int i = 0; i < 2; i++)
#pragma unroll
        for (int j = 0; j < 8; j++)
#pragma unroll
            for (int c = 0; c < 4; c++) acc[i][j][c] = 0.0f;

    gemm2(g_qh + (size_t)(b * SLEN + m0) * HID, g_ql + (size_t)(b * SLEN + m0) * HID,
          g_kf + (size_t)(b * SLEN + n0) * HID,
          HID, HID, HID / CHUNK_K, smem_u32(smem), acc);

    const int tid = threadIdx.x, wid = tid >> 5, lane = tid & 31;
    const int wm = (wid & 3) * 32, wn = (wid >> 2) * 64;
    const int g = lane >> 2, t2 = (lane & 3) * 2;
#pragma unroll
    for (int mt = 0; mt < 2; mt++)
#pragma unroll
        for (int ng = 0; ng < 8; ng++)
#pragma unroll
            for (int ci2 = 0; ci2 < 2; ci2++) {
                int m = m0 + wm + mt * 16 + g + ci2 * 8;
                int n = n0 + wn + ng * 8 + t2;
                float2 v = make_float2(acc[mt][ng][2 * ci2], acc[mt][ng][2 * ci2 + 1]);
                *(float2*)(g_S + ((size_t)b * SLEN + m) * SLEN + n) = v;
            }
}

__global__ void __launch_bounds__(256, 2) pv_tc(float* __restrict__ out) {
    extern __shared__ __align__(128) char smem[];
    float acc[2][8][4];
#pragma unroll
    for (int i = 0; i < 2; i++)
#pragma unroll
        for (int j = 0; j < 8; j++)
#pragma unroll
            for (int c = 0; c < 4; c++) acc[i][j][c] = 0.0f;

    const int n0 = blockIdx.x * 128;
    const int m0 = (int)(gridDim.y - 1 - blockIdx.y) * 128;   // heavy tiles first
    const int b  = blockIdx.z;
    const int nc = (m0 + 128) / CHUNK_K;

    gemm2(g_ph + (size_t)(b * SLEN + m0) * SLEN, g_pl + (size_t)(b * SLEN + m0) * SLEN,
          g_vt + (size_t)(b * HID + n0) * SLEN,
          SLEN, SLEN, nc, smem_u32(smem), acc);

    const int tid = threadIdx.x, wid = tid >> 5, lane = tid & 31;
    const int wm = (wid & 3) * 32, wn = (wid >> 2) * 64;
    const int g = lane >> 2, t2 = (lane & 3) * 2;
#pragma unroll
    for (int mt = 0; mt < 2; mt++)
#pragma unroll
        for (int ng = 0; ng < 8; ng++)
#pragma unroll
            for (int ci2 = 0; ci2 < 2; ci2++) {
                int m = m0 + wm + mt * 16 + g + ci2 * 8;
                int n = n0 + wn + ng * 8 + t2;
                float2 v = make_float2(acc[mt][ng][2 * ci2], acc[mt][ng][2 * ci2 + 1]);
                *(float2*)(out + ((size_t)b * SLEN + m) * HID + n) = v;
            }
}

// ---------------- softmax: S -> p hi/lo fp16, zero-padded to 128-tile end ----------------
__global__ void __launch_bounds__(256) softmax_kernel() {
    __shared__ float buf[SLEN];
    __shared__ float red[16];
    const int row = blockIdx.x;
    const int i   = row & (SLEN - 1);
    const int tid = threadIdx.x, wid = tid >> 5, lane = tid & 31;
    const float scale = 0.03125f;   // 1/sqrt(1024)
    const float* srow = g_S + (size_t)row * SLEN;
    const int n    = i + 1;
    const int jpad = ((i >> 7) + 1) << 7;

    float lm = -3.0e38f;
    for (int j = tid; j < n; j += 256) lm = fmaxf(lm, srow[j]);
#pragma unroll
    for (int o = 16; o; o >>= 1) lm = fmaxf(lm, __shfl_xor_sync(0xffffffffu, lm, o));
    if (lane == 0) red[wid] = lm;
    __syncthreads();
    if (tid == 0) {
        float m = red[0];
#pragma unroll
        for (int w = 1; w < 8; w++) m = fmaxf(m, red[w]);
        red[0] = m;
    }
    __syncthreads();
    const float mx = red[0];

    float ls = 0.0f;
    for (int j = tid; j < n; j += 256) {
        float e = __expf((srow[j] - mx) * scale);
        buf[j] = e;
        ls += e;
    }
#pragma unroll
    for (int o = 16; o; o >>= 1) ls += __shfl_xor_sync(0xffffffffu, ls, o);
    if (lane == 0) red[8 + wid] = ls;
    __syncthreads();
    if (tid == 0) {
        float s = 0.0f;
#pragma unroll
        for (int w = 0; w < 8; w++) s += red[8 + w];
        red[8] = 1.0f / s;
    }
    __syncthreads();
    const float inv = red[8];

    __half* ph = g_ph + (size_t)row * SLEN;
    __half* pl = g_pl + (size_t)row * SLEN;
    for (int j = tid; j < jpad; j += 256) {
        float p = (j < n) ? buf[j] * inv : 0.0f;
        __half hi = __float2half_rn(p);
        ph[j] = hi;
        pl[j] = __float2half_rn(p - __half2float(hi));
    }
}

// ---------------- splits + V transpose ----------------
__global__ void __launch_bounds__(256) split_x(const float* __restrict__ x) {
    size_t idx = (size_t)blockIdx.x * 256 + threadIdx.x;
    float v = x[idx];
    __half hi = __float2half_rn(v);
    g_xh[idx] = hi;
    g_xl[idx] = __float2half_rn(v - __half2float(hi));
}

__global__ void __launch_bounds__(256) conv_w(const float* __restrict__ W, int which) {
    size_t idx = (size_t)blockIdx.x * 256 + threadIdx.x;
    g_wf[which][idx] = __float2half_rn(W[idx]);
}

__global__ void __launch_bounds__(256) transpose_v() {
    __shared__ __half tv[32][33];
    const int b  = blockIdx.z;
    const int h0 = blockIdx.x * 32;
    const int s0 = blockIdx.y * 32;
    const int tx = threadIdx.x, ty = threadIdx.y;   // 32 x 8
    for (int r = ty; r < 32; r += 8)
        tv[r][tx] = g_vf[((size_t)b * SLEN + s0 + r) * HID + h0 + tx];
    __syncthreads();
    for (int r = ty; r < 32; r += 8)
        g_vt[((size_t)b * HID + h0 + r) * SLEN + s0 + tx] = tv[tx][r];
}

// =================================================================================
// Launch (launch index 5 = proj_tc so ncu -s 5 captures a GEMM kernel)
// =================================================================================
extern "C" void kernel_launch(void* const* d_in, const int* in_sizes, int n_in,
                              void* d_out, int out_size) {
    (void)in_sizes; (void)n_in; (void)out_size;
    const float* x  = (const float*)d_in[0];
    const float* Wq = (const float*)d_in[1];
    const float* Wk = (const float*)d_in[2];
    const float* Wv = (const float*)d_in[3];
    float* out = (float*)d_out;

    static bool attr_set = false;
    if (!attr_set) {
        cudaFuncSetAttribute(proj_tc,   cudaFuncAttributeMaxDynamicSharedMemorySize, E2_SMEM);
        cudaFuncSetAttribute(scores_tc, cudaFuncAttributeMaxDynamicSharedMemorySize, E2_SMEM);
        cudaFuncSetAttribute(pv_tc,     cudaFuncAttributeMaxDynamicSharedMemorySize, E2_SMEM);
        attr_set = true;
    }

    dim3 pgrid(HID / 128, MTOT / 128);                 // (8, 128)

    split_x<<<(MTOT * HID) / 256, 256>>>(x);           // 0
    conv_w<<<(HID * HID) / 256, 256>>>(Wq, 0);         // 1
    conv_w<<<(HID * HID) / 256, 256>>>(Wk, 1);         // 2
    conv_w<<<(HID * HID) / 256, 256>>>(Wv, 2);         // 3
    proj_tc<<<pgrid, 256, E2_SMEM>>>(0);               // 4  -> q
    proj_tc<<<pgrid, 256, E2_SMEM>>>(1);               // 5  -> k  (profiled)
    scores_tc<<<dim3(SLEN / 128, SLEN / 128, BATCH), 256, E2_SMEM>>>();   // 6
    proj_tc<<<pgrid, 256, E2_SMEM>>>(2);               // 7  -> v
    transpose_v<<<dim3(HID / 32, SLEN / 32, BATCH), dim3(32, 8)>>>();     // 8
    softmax_kernel<<<MTOT, 256>>>();                   // 9
    pv_tc<<<dim3(SLEN /  SLEN * (HID / 128), SLEN / 128, BATCH), 256, E2_SMEM>>>(out); // 10
}

// round 9
// speedup vs baseline: 3.0028x; 1.3162x over previous
#include <cuda_runtime.h>
#include <cuda_fp16.h>
#include <cstdint>

#define BATCH 4
#define SLEN  4096
#define HID   1024
#define MTOT  (BATCH * SLEN)   // 16384

// ---------------- static scratch (no runtime allocation) ----------------
__device__ __align__(16) __half g_xh[(size_t)MTOT * HID];
__device__ __align__(16) __half g_xl[(size_t)MTOT * HID];
__device__ __align__(16) __half g_wf[3][(size_t)HID * HID];  // Wq,Wk,Wv fp16 planes
__device__ __align__(16) __half g_qf[(size_t)MTOT * HID];    // q fp16 plane
__device__ __align__(16) __half g_kf[(size_t)MTOT * HID];    // k fp16 plane
__device__ __align__(16) __half g_vf[(size_t)MTOT * HID];    // v fp16 plane
__device__ __align__(16) __half g_vt[(size_t)MTOT * HID];    // v^T [b][h][s]
__device__ __align__(16) __half g_pf[(size_t)MTOT * SLEN];   // p fp16, zero-padded
__device__ __align__(16) float  g_S [(size_t)BATCH * SLEN * SLEN];

// ---------------- common helpers ----------------
__device__ __forceinline__ uint32_t smem_u32(const void* p) {
    return (uint32_t)__cvta_generic_to_shared(p);
}
#define CP_ASYNC16(dst, src) \
    asm volatile("cp.async.cg.shared.global [%0], [%1], 16;" :: "r"(dst), "l"(src) : "memory")
#define LDMX4(R0, R1, R2, R3, addr)                                              \
    asm volatile("ldmatrix.sync.aligned.m8n8.x4.shared.b16 {%0,%1,%2,%3}, [%4];" \
                 : "=r"(R0), "=r"(R1), "=r"(R2), "=r"(R3) : "r"(addr))
#define MMAF16(C, A0, A1, A2, A3, B0, B1)                                      \
    asm volatile("mma.sync.aligned.m16n8k16.row.col.f32.f16.f16.f32 "          \
                 "{%0,%1,%2,%3}, {%4,%5,%6,%7}, {%8,%9}, {%0,%1,%2,%3};"       \
                 : "+f"(C[0]), "+f"(C[1]), "+f"(C[2]), "+f"(C[3])              \
                 : "r"(A0), "r"(A1), "r"(A2), "r"(A3), "r"(B0), "r"(B1))

#define CHUNK_K 32

// =================================================================================
// Engine 2 (projections): C = (A_hi + A_lo) . B^T, B single fp16 plane.
// 256 thr, warps 4m x 2n (warp tile 32x64), 2-stage, occ 2.
// A rows: 144B [hi 64B | lo 64B | pad]; B rows: 80B.
// =================================================================================
#define E2_SMO_B   18432
#define E2_STAGE   28672
#define E2_SMEM    (2 * E2_STAGE)        // 57344

__device__ __forceinline__ void e2_issue(uint32_t st,
                                         const __half* __restrict__ Ahi, const __half* __restrict__ Alo,
                                         const __half* __restrict__ B,
                                         int ldA, int ldB, int kc, int tid) {
    const int col0 = kc * CHUNK_K;
#pragma unroll
    for (int i = 0; i < 4; i++) {
        int id = tid + 256 * i;
        int row = id >> 3, plane = (id >> 2) & 1, quad = id & 3;
        const __half* src = (plane ? Alo : Ahi) + (size_t)row * ldA + col0 + quad * 8;
        CP_ASYNC16(st + row * 144 + plane * 64 + quad * 16, src);
    }
#pragma unroll
    for (int i = 0; i < 2; i++) {
        int id = tid + 256 * i;
        int row = id >> 2, quad = id & 3;
        const __half* src = B + (size_t)row * ldB + col0 + quad * 8;
        CP_ASYNC16(st + E2_SMO_B + row * 80 + quad * 16, src);
    }
    asm volatile("cp.async.commit_group;" ::: "memory");
}

__device__ __forceinline__ void gemm2(const __half* __restrict__ Ahi, const __half* __restrict__ Alo,
                                      const __half* __restrict__ B,
                                      int ldA, int ldB, int nChunks,
                                      uint32_t sb, float (&acc)[2][8][4]) {
    const int tid  = threadIdx.x;
    const int wid  = tid >> 5;
    const int lane = tid & 31;
    const int wm   = (wid & 3) * 32;
    const int wn   = (wid >> 2) * 64;
    const int lrow = lane & 15;
    const int lkB  = (lane >> 4) * 8;

    e2_issue(sb, Ahi, Alo, B, ldA, ldB, 0, tid);

    for (int kc = 0; kc < nChunks; kc++) {
        asm volatile("cp.async.wait_group 0;" ::: "memory");
        __syncthreads();

        if (kc + 1 < nChunks)
            e2_issue(sb + ((kc + 1) & 1) * E2_STAGE, Ahi, Alo, B, ldA, ldB, kc + 1, tid);

        const uint32_t sA = sb + (kc & 1) * E2_STAGE;
        const uint32_t sB = sA + E2_SMO_B;
#pragma unroll
        for (int ks = 0; ks < 2; ks++) {
            uint32_t a[2][2][4];
#pragma unroll
            for (int mt = 0; mt < 2; mt++) {
                uint32_t ad = sA + ((wm + mt * 16 + lrow) * 72 + ks * 16 + lkB) * 2;
                LDMX4(a[0][mt][0], a[0][mt][1], a[0][mt][2], a[0][mt][3], ad);
                LDMX4(a[1][mt][0], a[1][mt][1], a[1][mt][2], a[1][mt][3], ad + 64);
            }
            uint32_t b[4][4];
#pragma unroll
            for (int g = 0; g < 4; g++) {
                uint32_t bd = sB + (wn + g * 16 + lrow) * 80 + (ks * 16 + lkB) * 2;
                LDMX4(b[g][0], b[g][1], b[g][2], b[g][3], bd);
            }
#pragma unroll
            for (int pa = 0; pa < 2; pa++)
#pragma unroll
                for (int mt = 0; mt < 2; mt++)
#pragma unroll
                    for (int g = 0; g < 4; g++) {
                        MMAF16(acc[mt][2 * g],
                               a[pa][mt][0], a[pa][mt][1], a[pa][mt][2], a[pa][mt][3],
                               b[g][0], b[g][2]);
                        MMAF16(acc[mt][2 * g + 1],
                               a[pa][mt][0], a[pa][mt][1], a[pa][mt][2], a[pa][mt][3],
                               b[g][1], b[g][3]);
                    }
        }
    }
    __syncthreads();
}

// =================================================================================
// Engine 1 (scores / PV): C = A . B^T, both single fp16 planes.
// 256 thr, warps 4m x 2n (warp tile 32x64), 2-stage, occ 2.
// A and B rows: 80B [64B data | 16B pad].
// =================================================================================
#define E1_SMO_B   10240                 // 128*80
#define E1_STAGE   20480
#define E1_SMEM    (2 * E1_STAGE)        // 40960

__device__ __forceinline__ void e1_issue(uint32_t st,
                                         const __half* __restrict__ A,
                                         const __half* __restrict__ B,
                                         int ldA, int ldB, int kc, int tid) {
    const int col0 = kc * CHUNK_K;
#pragma unroll
    for (int i = 0; i < 2; i++) {
        int id = tid + 256 * i;
        int row = id >> 2, quad = id & 3;
        const __half* src = A + (size_t)row * ldA + col0 + quad * 8;
        CP_ASYNC16(st + row * 80 + quad * 16, src);
    }
#pragma unroll
    for (int i = 0; i < 2; i++) {
        int id = tid + 256 * i;
        int row = id >> 2, quad = id & 3;
        const __half* src = B + (size_t)row * ldB + col0 + quad * 8;
        CP_ASYNC16(st + E1_SMO_B + row * 80 + quad * 16, src);
    }
    asm volatile("cp.async.commit_group;" ::: "memory");
}

__device__ __forceinline__ void gemm1(const __half* __restrict__ A,
                                      const __half* __restrict__ B,
                                      int ldA, int ldB, int nChunks,
                                      uint32_t sb, float (&acc)[2][8][4]) {
    const int tid  = threadIdx.x;
    const int wid  = tid >> 5;
    const int lane = tid & 31;
    const int wm   = (wid & 3) * 32;
    const int wn   = (wid >> 2) * 64;
    const int lrow = lane & 15;
    const int lkB  = (lane >> 4) * 8;

    e1_issue(sb, A, B, ldA, ldB, 0, tid);

    for (int kc = 0; kc < nChunks; kc++) {
        asm volatile("cp.async.wait_group 0;" ::: "memory");
        __syncthreads();

        if (kc + 1 < nChunks)
            e1_issue(sb + ((kc + 1) & 1) * E1_STAGE, A, B, ldA, ldB, kc + 1, tid);

        const uint32_t sA = sb + (kc & 1) * E1_STAGE;
        const uint32_t sB = sA + E1_SMO_B;
#pragma unroll
        for (int ks = 0; ks < 2; ks++) {
            uint32_t a[2][4];
#pragma unroll
            for (int mt = 0; mt < 2; mt++) {
                uint32_t ad = sA + (wm + mt * 16 + lrow) * 80 + (ks * 16 + lkB) * 2;
                LDMX4(a[mt][0], a[mt][1], a[mt][2], a[mt][3], ad);
            }
            uint32_t b[4][4];
#pragma unroll
            for (int g = 0; g < 4; g++) {
                uint32_t bd = sB + (wn + g * 16 + lrow) * 80 + (ks * 16 + lkB) * 2;
                LDMX4(b[g][0], b[g][1], b[g][2], b[g][3], bd);
            }
#pragma unroll
            for (int mt = 0; mt < 2; mt++)
#pragma unroll
                for (int g = 0; g < 4; g++) {
                    MMAF16(acc[mt][2 * g],
                           a[mt][0], a[mt][1], a[mt][2], a[mt][3],
                           b[g][0], b[g][2]);
                    MMAF16(acc[mt][2 * g + 1],
                           a[mt][0], a[mt][1], a[mt][2], a[mt][3],
                           b[g][1], b[g][3]);
                }
        }
    }
    __syncthreads();
}

// =================================================================================
// GEMM kernels
// =================================================================================
__global__ void __launch_bounds__(256, 2) proj_tc(int mode) {
    extern __shared__ __align__(128) char smem[];
    float acc[2][8][4];
#pragma unroll
    for (int i = 0; i < 2; i++)
#pragma unroll
        for (int j = 0; j < 8; j++)
#pragma unroll
            for (int c = 0; c < 4; c++) acc[i][j][c] = 0.0f;

    const int m0 = blockIdx.y * 128;
    const int n0 = blockIdx.x * 128;
    gemm2(g_xh + (size_t)m0 * HID, g_xl + (size_t)m0 * HID,
          g_wf[mode] + (size_t)n0 * HID,
          HID, HID, HID / CHUNK_K, smem_u32(smem), acc);

    __half* dst = (mode == 0) ? g_qf : (mode == 1) ? g_kf : g_vf;

    const int tid = threadIdx.x, wid = tid >> 5, lane = tid & 31;
    const int wm = (wid & 3) * 32, wn = (wid >> 2) * 64;
    const int g = lane >> 2, t2 = (lane & 3) * 2;
#pragma unroll
    for (int mt = 0; mt < 2; mt++)
#pragma unroll
        for (int ng = 0; ng < 8; ng++)
#pragma unroll
            for (int ci = 0; ci < 4; ci++) {
                int m = m0 + wm + mt * 16 + g + ((ci >> 1) << 3);
                int n = n0 + wn + ng * 8 + t2 + (ci & 1);
                dst[(size_t)m * HID + n] = __float2half_rn(acc[mt][ng][ci]);
            }
}

__global__ void __launch_bounds__(256, 2) scores_tc() {
    const int m0 = blockIdx.y * 128;
    const int n0 = blockIdx.x * 128;
    if (n0 > m0 + 127) return;                 // fully masked tile
    const int b = blockIdx.z;

    extern __shared__ __align__(128) char smem[];
    float acc[2][8][4];
#pragma unroll
    for (int i = 0; i < 2; i++)
#pragma unroll
        for (int j = 0; j < 8; j++)
#pragma unroll
            for (int c = 0; c < 4; c++) acc[i][j][c] = 0.0f;

    gemm1(g_qf + (size_t)(b * SLEN + m0) * HID,
          g_kf + (size_t)(b * SLEN + n0) * HID,
          HID, HID, HID / CHUNK_K, smem_u32(smem), acc);

    const int tid = threadIdx.x, wid = tid >> 5, lane = tid & 31;
    const int wm = (wid & 3) * 32, wn = (wid >> 2) * 64;
    const int g = lane >> 2, t2 = (lane & 3) * 2;
#pragma unroll
    for (int mt = 0; mt < 2; mt++)
#pragma unroll
        for (int ng = 0; ng < 8; ng++)
#pragma unroll
            for (int ci2 = 0; ci2 < 2; ci2++) {
                int m = m0 + wm + mt * 16 + g + ci2 * 8;
                int n = n0 + wn + ng * 8 + t2;
                float2 v = make_float2(acc[mt][ng][2 * ci2], acc[mt][ng][2 * ci2 + 1]);
                *(float2*)(g_S + ((size_t)b * SLEN + m) * SLEN + n) = v;
            }
}

__global__ void __launch_bounds__(256, 2) pv_tc(float* __restrict__ out) {
    extern __shared__ __align__(128) char smem[];
    float acc[2][8][4];
#pragma unroll
    for (int i = 0; i < 2; i++)
#pragma unroll
        for (int j = 0; j < 8; j++)
#pragma unroll
            for (int c = 0; c < 4; c++) acc[i][j][c] = 0.0f;

    const int n0 = blockIdx.x * 128;
    const int m0 = (int)(gridDim.y - 1 - blockIdx.y) * 128;   // heavy tiles first
    const int b  = blockIdx.z;
    const int nc = (m0 + 128) / CHUNK_K;

    gemm1(g_pf + (size_t)(b * SLEN + m0) * SLEN,
          g_vt + (size_t)(b * HID + n0) * SLEN,
          SLEN, SLEN, nc, smem_u32(smem), acc);

    const int tid = threadIdx.x, wid = tid >> 5, lane = tid & 31;
    const int wm = (wid & 3) * 32, wn = (wid >> 2) * 64;
    const int g = lane >> 2, t2 = (lane & 3) * 2;
#pragma unroll
    for (int mt = 0; mt < 2; mt++)
#pragma unroll
        for (int ng = 0; ng < 8; ng++)
#pragma unroll
            for (int ci2 = 0; ci2 < 2; ci2++) {
                int m = m0 + wm + mt * 16 + g + ci2 * 8;
                int n = n0 + wn + ng * 8 + t2;
                float2 v = make_float2(acc[mt][ng][2 * ci2], acc[mt][ng][2 * ci2 + 1]);
                *(float2*)(out + ((size_t)b * SLEN + m) * HID + n) = v;
            }
}

// ---------------- softmax: S -> p fp16, zero-padded to 128-tile end ----------------
__global__ void __launch_bounds__(256) softmax_kernel() {
    __shared__ float buf[SLEN];
    __shared__ float red[16];
    const int row = blockIdx.x;
    const int i   = row & (SLEN - 1);
    const int tid = threadIdx.x, wid = tid >> 5, lane = tid & 31;
    const float scale = 0.03125f;   // 1/sqrt(1024)
    const float* srow = g_S + (size_t)row * SLEN;
    const int n    = i + 1;
    const int jpad = ((i >> 7) + 1) << 7;

    float lm = -3.0e38f;
    for (int j = tid; j < n; j += 256) lm = fmaxf(lm, srow[j]);
#pragma unroll
    for (int o = 16; o; o >>= 1) lm = fmaxf(lm, __shfl_xor_sync(0xffffffffu, lm, o));
    if (lane == 0) red[wid] = lm;
    __syncthreads();
    if (tid == 0) {
        float m = red[0];
#pragma unroll
        for (int w = 1; w < 8; w++) m = fmaxf(m, red[w]);
        red[0] = m;
    }
    __syncthreads();
    const float mx = red[0];

    float ls = 0.0f;
    for (int j = tid; j < n; j += 256) {
        float e = __expf((srow[j] - mx) * scale);
        buf[j] = e;
        ls += e;
    }
#pragma unroll
    for (int o = 16; o; o >>= 1) ls += __shfl_xor_sync(0xffffffffu, ls, o);
    if (lane == 0) red[8 + wid] = ls;
    __syncthreads();
    if (tid == 0) {
        float s = 0.0f;
#pragma unroll
        for (int w = 0; w < 8; w++) s += red[8 + w];
        red[8] = 1.0f / s;
    }
    __syncthreads();
    const float inv = red[8];

    __half* pf = g_pf + (size_t)row * SLEN;
    for (int j = tid; j < jpad; j += 256) {
        float p = (j < n) ? buf[j] * inv : 0.0f;
        pf[j] = __float2half_rn(p);
    }
}

// ---------------- splits + V transpose ----------------
__global__ void __launch_bounds__(256) split_x(const float* __restrict__ x) {
    size_t idx = (size_t)blockIdx.x * 256 + threadIdx.x;
    float v = x[idx];
    __half hi = __float2half_rn(v);
    g_xh[idx] = hi;
    g_xl[idx] = __float2half_rn(v - __half2float(hi));
}

__global__ void __launch_bounds__(256) conv_w(const float* __restrict__ W, int which) {
    size_t idx = (size_t)blockIdx.x * 256 + threadIdx.x;
    g_wf[which][idx] = __float2half_rn(W[idx]);
}

__global__ void __launch_bounds__(256) transpose_v() {
    __shared__ __half tv[32][33];
    const int b  = blockIdx.z;
    const int h0 = blockIdx.x * 32;
    const int s0 = blockIdx.y * 32;
    const int tx = threadIdx.x, ty = threadIdx.y;   // 32 x 8
    for (int r = ty; r < 32; r += 8)
        tv[r][tx] = g_vf[((size_t)b * SLEN + s0 + r) * HID + h0 + tx];
    __syncthreads();
    for (int r = ty; r < 32; r += 8)
        g_vt[((size_t)b * HID + h0 + r) * SLEN + s0 + tx] = tv[tx][r];
}

// =================================================================================
// Launch
// =================================================================================
extern "C" void kernel_launch(void* const* d_in, const int* in_sizes, int n_in,
                              void* d_out, int out_size) {
    (void)in_sizes; (void)n_in; (void)out_size;
    const float* x  = (const float*)d_in[0];
    const float* Wq = (const float*)d_in[1];
    const float* Wk = (const float*)d_in[2];
    const float* Wv = (const float*)d_in[3];
    float* out = (float*)d_out;

    static bool attr_set = false;
    if (!attr_set) {
        cudaFuncSetAttribute(proj_tc,   cudaFuncAttributeMaxDynamicSharedMemorySize, E2_SMEM);
        cudaFuncSetAttribute(scores_tc, cudaFuncAttributeMaxDynamicSharedMemorySize, E1_SMEM);
        cudaFuncSetAttribute(pv_tc,     cudaFuncAttributeMaxDynamicSharedMemorySize, E1_SMEM);
        attr_set = true;
    }

    dim3 pgrid(HID / 128, MTOT / 128);                 // (8, 128)

    split_x<<<(MTOT * HID) / 256, 256>>>(x);           // 0
    conv_w<<<(HID * HID) / 256, 256>>>(Wq, 0);         // 1
    conv_w<<<(HID * HID) / 256, 256>>>(Wk, 1);         // 2
    conv_w<<<(HID * HID) / 256, 256>>>(Wv, 2);         // 3
    proj_tc<<<pgrid, 256, E2_SMEM>>>(0);               // 4  -> q
    proj_tc<<<pgrid, 256, E2_SMEM>>>(1);               // 5  -> k
    scores_tc<<<dim3(SLEN / 128, SLEN / 128, BATCH), 256, E1_SMEM>>>();   // 6
    proj_tc<<<pgrid, 256, E2_SMEM>>>(2);               // 7  -> v
    transpose_v<<<dim3(HID / 32, SLEN / 32, BATCH), dim3(32, 8)>>>();     // 8
    softmax_kernel<<<MTOT, 256>>>();                   // 9
    pv_tc<<<dim3(HID / 128, SLEN / 128, BATCH), 256, E1_SMEM>>>(out);     // 10
}

// round 11
// speedup vs baseline: 3.1780x; 1.0583x over previous
#include <cuda_runtime.h>
#include <cuda_fp16.h>
#include <cstdint>

#define BATCH 4
#define SLEN  4096
#define HID   1024
#define MTOT  (BATCH * SLEN)   // 16384

// ---------------- static scratch (no runtime allocation) ----------------
__device__ __align__(16) __half g_xh[(size_t)MTOT * HID];
__device__ __align__(16) __half g_xl[(size_t)MTOT * HID];
__device__ __align__(16) __half g_wf[3][(size_t)HID * HID];  // Wq,Wk,Wv fp16 planes
__device__ __align__(16) __half g_qf[(size_t)MTOT * HID];    // q fp16 plane
__device__ __align__(16) __half g_kf[(size_t)MTOT * HID];    // k fp16 plane
__device__ __align__(16) __half g_vt[(size_t)MTOT * HID];    // v^T [b][h][s]
__device__ __align__(16) __half g_pf[(size_t)MTOT * SLEN];   // p fp16, zero-padded
__device__ __align__(16) __half g_Sh[(size_t)BATCH * SLEN * SLEN];  // scaled scores fp16

// ---------------- common helpers ----------------
__device__ __forceinline__ uint32_t smem_u32(const void* p) {
    return (uint32_t)__cvta_generic_to_shared(p);
}
#define CP_ASYNC16(dst, src) \
    asm volatile("cp.async.cg.shared.global [%0], [%1], 16;" :: "r"(dst), "l"(src) : "memory")
#define LDMX4(R0, R1, R2, R3, addr)                                              \
    asm volatile("ldmatrix.sync.aligned.m8n8.x4.shared.b16 {%0,%1,%2,%3}, [%4];" \
                 : "=r"(R0), "=r"(R1), "=r"(R2), "=r"(R3) : "r"(addr))
#define MMAF16(C, A0, A1, A2, A3, B0, B1)                                      \
    asm volatile("mma.sync.aligned.m16n8k16.row.col.f32.f16.f16.f32 "          \
                 "{%0,%1,%2,%3}, {%4,%5,%6,%7}, {%8,%9}, {%0,%1,%2,%3};"       \
                 : "+f"(C[0]), "+f"(C[1]), "+f"(C[2]), "+f"(C[3])              \
                 : "r"(A0), "r"(A1), "r"(A2), "r"(A3), "r"(B0), "r"(B1))

#define CHUNK_K 32

// =================================================================================
// Engine 2 (projections): C = (A_hi + A_lo) . B^T, B single fp16 plane.
// 256 thr, warps 4m x 2n (warp tile 32x64), 2-stage, occ 2.
// =================================================================================
#define E2_SMO_B   18432
#define E2_STAGE   28672
#define E2_SMEM    (2 * E2_STAGE)        // 57344

__device__ __forceinline__ void e2_issue(uint32_t st,
                                         const __half* __restrict__ Ahi, const __half* __restrict__ Alo,
                                         const __half* __restrict__ B,
                                         int ldA, int ldB, int kc, int tid) {
    const int col0 = kc * CHUNK_K;
#pragma unroll
    for (int i = 0; i < 4; i++) {
        int id = tid + 256 * i;
        int row = id >> 3, plane = (id >> 2) & 1, quad = id & 3;
        const __half* src = (plane ? Alo : Ahi) + (size_t)row * ldA + col0 + quad * 8;
        CP_ASYNC16(st + row * 144 + plane * 64 + quad * 16, src);
    }
#pragma unroll
    for (int i = 0; i < 2; i++) {
        int id = tid + 256 * i;
        int row = id >> 2, quad = id & 3;
        const __half* src = B + (size_t)row * ldB + col0 + quad * 8;
        CP_ASYNC16(st + E2_SMO_B + row * 80 + quad * 16, src);
    }
    asm volatile("cp.async.commit_group;" ::: "memory");
}

__device__ __forceinline__ void gemm2(const __half* __restrict__ Ahi, const __half* __restrict__ Alo,
                                      const __half* __restrict__ B,
                                      int ldA, int ldB, int nChunks,
                                      uint32_t sb, float (&acc)[2][8][4]) {
    const int tid  = threadIdx.x;
    const int wid  = tid >> 5;
    const int lane = tid & 31;
    const int wm   = (wid & 3) * 32;
    const int wn   = (wid >> 2) * 64;
    const int lrow = lane & 15;
    const int lkB  = (lane >> 4) * 8;

    e2_issue(sb, Ahi, Alo, B, ldA, ldB, 0, tid);

    for (int kc = 0; kc < nChunks; kc++) {
        asm volatile("cp.async.wait_group 0;" ::: "memory");
        __syncthreads();

        if (kc + 1 < nChunks)
            e2_issue(sb + ((kc + 1) & 1) * E2_STAGE, Ahi, Alo, B, ldA, ldB, kc + 1, tid);

        const uint32_t sA = sb + (kc & 1) * E2_STAGE;
        const uint32_t sB = sA + E2_SMO_B;
#pragma unroll
        for (int ks = 0; ks < 2; ks++) {
            uint32_t a[2][2][4];
#pragma unroll
            for (int mt = 0; mt < 2; mt++) {
                uint32_t ad = sA + ((wm + mt * 16 + lrow) * 72 + ks * 16 + lkB) * 2;
                LDMX4(a[0][mt][0], a[0][mt][1], a[0][mt][2], a[0][mt][3], ad);
                LDMX4(a[1][mt][0], a[1][mt][1], a[1][mt][2], a[1][mt][3], ad + 64);
            }
            uint32_t b[4][4];
#pragma unroll
            for (int g = 0; g < 4; g++) {
                uint32_t bd = sB + (wn + g * 16 + lrow) * 80 + (ks * 16 + lkB) * 2;
                LDMX4(b[g][0], b[g][1], b[g][2], b[g][3], bd);
            }
#pragma unroll
            for (int pa = 0; pa < 2; pa++)
#pragma unroll
                for (int mt = 0; mt < 2; mt++)
#pragma unroll
                    for (int g = 0; g < 4; g++) {
                        MMAF16(acc[mt][2 * g],
                               a[pa][mt][0], a[pa][mt][1], a[pa][mt][2], a[pa][mt][3],
                               b[g][0], b[g][2]);
                        MMAF16(acc[mt][2 * g + 1],
                               a[pa][mt][0], a[pa][mt][1], a[pa][mt][2], a[pa][mt][3],
                               b[g][1], b[g][3]);
                    }
        }
    }
    __syncthreads();
}

// =================================================================================
// Engine 1 (scores / PV): C = A . B^T, both single fp16 planes.
// =================================================================================
#define E1_SMO_B   10240
#define E1_STAGE   20480
#define E1_SMEM    (2 * E1_STAGE)        // 40960

__device__ __forceinline__ void e1_issue(uint32_t st,
                                         const __half* __restrict__ A,
                                         const __half* __restrict__ B,
                                         int ldA, int ldB, int kc, int tid) {
    const int col0 = kc * CHUNK_K;
#pragma unroll
    for (int i = 0; i < 2; i++) {
        int id = tid + 256 * i;
        int row = id >> 2, quad = id & 3;
        const __half* src = A + (size_t)row * ldA + col0 + quad * 8;
        CP_ASYNC16(st + row * 80 + quad * 16, src);
    }
#pragma unroll
    for (int i = 0; i < 2; i++) {
        int id = tid + 256 * i;
        int row = id >> 2, quad = id & 3;
        const __half* src = B + (size_t)row * ldB + col0 + quad * 8;
        CP_ASYNC16(st + E1_SMO_B + row * 80 + quad * 16, src);
    }
    asm volatile("cp.async.commit_group;" ::: "memory");
}

__device__ __forceinline__ void gemm1(const __half* __restrict__ A,
                                      const __half* __restrict__ B,
                                      int ldA, int ldB, int nChunks,
                                      uint32_t sb, float (&acc)[2][8][4]) {
    const int tid  = threadIdx.x;
    const int wid  = tid >> 5;
    const int lane = tid & 31;
    const int wm   = (wid & 3) * 32;
    const int wn   = (wid >> 2) * 64;
    const int lrow = lane & 15;
    const int lkB  = (lane >> 4) * 8;

    e1_issue(sb, A, B, ldA, ldB, 0, tid);

    for (int kc = 0; kc < nChunks; kc++) {
        asm volatile("cp.async.wait_group 0;" ::: "memory");
        __syncthreads();

        if (kc + 1 < nChunks)
            e1_issue(sb + ((kc + 1) & 1) * E1_STAGE, A, B, ldA, ldB, kc + 1, tid);

        const uint32_t sA = sb + (kc & 1) * E1_STAGE;
        const uint32_t sB = sA + E1_SMO_B;
#pragma unroll
        for (int ks = 0; ks < 2; ks++) {
            uint32_t a[2][4];
#pragma unroll
            for (int mt = 0; mt < 2; mt++) {
                uint32_t ad = sA + (wm + mt * 16 + lrow) * 80 + (ks * 16 + lkB) * 2;
                LDMX4(a[mt][0], a[mt][1], a[mt][2], a[mt][3], ad);
            }
            uint32_t b[4][4];
#pragma unroll
            for (int g = 0; g < 4; g++) {
                uint32_t bd = sB + (wn + g * 16 + lrow) * 80 + (ks * 16 + lkB) * 2;
                LDMX4(b[g][0], b[g][1], b[g][2], b[g][3], bd);
            }
#pragma unroll
            for (int mt = 0; mt < 2; mt++)
#pragma unroll
                for (int g = 0; g < 4; g++) {
                    MMAF16(acc[mt][2 * g],
                           a[mt][0], a[mt][1], a[mt][2], a[mt][3],
                           b[g][0], b[g][2]);
                    MMAF16(acc[mt][2 * g + 1],
                           a[mt][0], a[mt][1], a[mt][2], a[mt][3],
                           b[g][1], b[g][3]);
                }
        }
    }
    __syncthreads();
}

// =================================================================================
// GEMM kernels
// =================================================================================
#define TSTR 130   // transpose staging stride (halfs): 65 words, odd -> conflict-free 32-bit

__global__ void __launch_bounds__(256, 2) proj_tc(int mode) {
    extern __shared__ __align__(128) char smem[];
    float acc[2][8][4];
#pragma unroll
    for (int i = 0; i < 2; i++)
#pragma unroll
        for (int j = 0; j < 8; j++)
#pragma unroll
            for (int c = 0; c < 4; c++) acc[i][j][c] = 0.0f;

    const int m0 = blockIdx.y * 128;
    const int n0 = blockIdx.x * 128;
    gemm2(g_xh + (size_t)m0 * HID, g_xl + (size_t)m0 * HID,
          g_wf[mode] + (size_t)n0 * HID,
          HID, HID, HID / CHUNK_K, smem_u32(smem), acc);

    const int tid = threadIdx.x, wid = tid >> 5, lane = tid & 31;
    const int wm = (wid & 3) * 32, wn = (wid >> 2) * 64;
    const int g = lane >> 2, t2 = (lane & 3) * 2;

    if (mode != 2) {
        __half* dst = (mode == 0) ? g_qf : g_kf;
#pragma unroll
        for (int mt = 0; mt < 2; mt++)
#pragma unroll
            for (int ng = 0; ng < 8; ng++)
#pragma unroll
                for (int ci = 0; ci < 4; ci++) {
                    int m = m0 + wm + mt * 16 + g + ((ci >> 1) << 3);
                    int n = n0 + wn + ng * 8 + t2 + (ci & 1);
                    dst[(size_t)m * HID + n] = __float2half_rn(acc[mt][ng][ci]);
                }
    } else {
        // fused transpose: stage tile into smem as [n_local][m_local], then write v^T
        __half* ts = (__half*)smem;
#pragma unroll
        for (int mt = 0; mt < 2; mt++)
#pragma unroll
            for (int ng = 0; ng < 8; ng++)
#pragma unroll
                for (int ci = 0; ci < 4; ci++) {
                    int ml = wm + mt * 16 + g + ((ci >> 1) << 3);
                    int nl = wn + ng * 8 + t2 + (ci & 1);
                    ts[nl * TSTR + ml] = __float2half_rn(acc[mt][ng][ci]);
                }
        __syncthreads();
        const int b  = m0 >> 12;            // batch of this m-tile
        const int s0 = m0 & (SLEN - 1);     // seq offset within batch
        const int r    = tid & 127;         // h row within tile
        const int part = tid >> 7;          // 0/1 -> 64-half halves
        __half* drow = g_vt + ((size_t)b * HID + n0 + r) * SLEN + s0 + part * 64;
        const __half* srow = ts + r * TSTR + part * 64;
        // shared side: scalar 32-bit loads (4B aligned, odd word stride -> conflict-free)
        // global side: 16B vector stores (128B-aligned base)
#pragma unroll
        for (int k = 0; k < 8; k++) {
            uint32_t v0, v1, v2, v3;
            uint32_t ad = smem_u32(srow + k * 8);
            asm volatile("ld.shared.b32 %0, [%1];"      : "=r"(v0) : "r"(ad));
            asm volatile("ld.shared.b32 %0, [%1+4];"    : "=r"(v1) : "r"(ad));
            asm volatile("ld.shared.b32 %0, [%1+8];"    : "=r"(v2) : "r"(ad));
            asm volatile("ld.shared.b32 %0, [%1+12];"   : "=r"(v3) : "r"(ad));
            *(uint4*)(drow + k * 8) = make_uint4(v0, v1, v2, v3);
        }
    }
}

__global__ void __launch_bounds__(256, 2) scores_tc() {
    const int m0 = blockIdx.y * 128;
    const int n0 = blockIdx.x * 128;
    if (n0 > m0 + 127) return;                 // fully masked tile
    const int b = blockIdx.z;

    extern __shared__ __align__(128) char smem[];
    float acc[2][8][4];
#pragma unroll
    for (int i = 0; i < 2; i++)
#pragma unroll
        for (int j = 0; j < 8; j++)
#pragma unroll
            for (int c = 0; c < 4; c++) acc[i][j][c] = 0.0f;

    gemm1(g_qf + (size_t)(b * SLEN + m0) * HID,
          g_kf + (size_t)(b * SLEN + n0) * HID,
          HID, HID, HID / CHUNK_K, smem_u32(smem), acc);

    const float scale = 0.03125f;   // 1/sqrt(1024)
    const int tid = threadIdx.x, wid = tid >> 5, lane = tid & 31;
    const int wm = (wid & 3) * 32, wn = (wid >> 2) * 64;
    const int g = lane >> 2, t2 = (lane & 3) * 2;
#pragma unroll
    for (int mt = 0; mt < 2; mt++)
#pragma unroll
        for (int ng = 0; ng < 8; ng++)
#pragma unroll
            for (int ci2 = 0; ci2 < 2; ci2++) {
                int m = m0 + wm + mt * 16 + g + ci2 * 8;
                int n = n0 + wn + ng * 8 + t2;
                __half2 h = __floats2half2_rn(acc[mt][ng][2 * ci2] * scale,
                                              acc[mt][ng][2 * ci2 + 1] * scale);
                *(__half2*)(g_Sh + ((size_t)b * SLEN + m) * SLEN + n) = h;
            }
}

__global__ void __launch_bounds__(256, 2) pv_tc(float* __restrict__ out) {
    extern __shared__ __align__(128) char smem[];
    float acc[2][8][4];
#pragma unroll
    for (int i = 0; i < 2; i++)
#pragma unroll
        for (int j = 0; j < 8; j++)
#pragma unroll
            for (int c = 0; c < 4; c++) acc[i][j][c] = 0.0f;

    const int n0 = blockIdx.x * 128;
    const int m0 = (int)(gridDim.y - 1 - blockIdx.y) * 128;   // heavy tiles first
    const int b  = blockIdx.z;
    const int nc = (m0 + 128) / CHUNK_K;

    gemm1(g_pf + (size_t)(b * SLEN + m0) * SLEN,
          g_vt + (size_t)(b * HID + n0) * SLEN,
          SLEN, SLEN, nc, smem_u32(smem), acc);

    const int tid = threadIdx.x, wid = tid >> 5, lane = tid & 31;
    const int wm = (wid & 3) * 32, wn = (wid >> 2) * 64;
    const int g = lane >> 2, t2 = (lane & 3) * 2;
#pragma unroll
    for (int mt = 0; mt < 2; mt++)
#pragma unroll
        for (int ng = 0; ng < 8; ng++)
#pragma unroll
            for (int ci2 = 0; ci2 < 2; ci2++) {
                int m = m0 + wm + mt * 16 + g + ci2 * 8;
                int n = n0 + wn + ng * 8 + t2;
                float2 v = make_float2(acc[mt][ng][2 * ci2], acc[mt][ng][2 * ci2 + 1]);
                *(float2*)(out + ((size_t)b * SLEN + m) * HID + n) = v;
            }
}

// ---------------- softmax: Sh (scaled fp16) -> p fp16, single global pass ----------------
__global__ void __launch_bounds__(256) softmax_kernel() {
    __shared__ float red[16];
    const int row = blockIdx.x;
    const int i   = row & (SLEN - 1);
    const int tid = threadIdx.x, wid = tid >> 5, lane = tid & 31;
    const int n    = i + 1;
    const int jpad = ((i >> 7) + 1) << 7;
    const __half2* srow2 = (const __half2*)(g_Sh + (size_t)row * SLEN);

    // load (coalesced half2), convert, local max
    float2 v[8];
    float lm = -3.0e38f;
#pragma unroll
    for (int it = 0; it < 8; it++) {
        int j2 = tid + 256 * it;
        int j  = 2 * j2;
        if (j < n) {
            float2 f = __half22float2(srow2[j2]);
            if (j + 1 >= n) f.y = -3.0e38f;
            v[it] = f;
            lm = fmaxf(lm, fmaxf(f.x, f.y));
        } else {
            v[it] = make_float2(-3.0e38f, -3.0e38f);
        }
    }
#pragma unroll
    for (int o = 16; o; o >>= 1) lm = fmaxf(lm, __shfl_xor_sync(0xffffffffu, lm, o));
    if (lane == 0) red[wid] = lm;
    __syncthreads();
    if (tid == 0) {
        float m = red[0];
#pragma unroll
        for (int w = 1; w < 8; w++) m = fmaxf(m, red[w]);
        red[0] = m;
    }
    __syncthreads();
    const float mx = red[0];

    // exp from registers + sum
    float ls = 0.0f;
#pragma unroll
    for (int it = 0; it < 8; it++) {
        float ex = (v[it].x > -1.0e38f) ? __expf(v[it].x - mx) : 0.0f;
        float ey = (v[it].y > -1.0e38f) ? __expf(v[it].y - mx) : 0.0f;
        v[it].x = ex; v[it].y = ey;
        ls += ex + ey;
    }
#pragma unroll
    for (int o = 16; o; o >>= 1) ls += __shfl_xor_sync(0xffffffffu, ls, o);
    if (lane == 0) red[8 + wid] = ls;
    __syncthreads();
    if (tid == 0) {
        float s = 0.0f;
#pragma unroll
        for (int w = 0; w < 8; w++) s += red[8 + w];
        red[8] = 1.0f / s;
    }
    __syncthreads();
    const float inv = red[8];

    __half2* pf2 = (__half2*)(g_pf + (size_t)row * SLEN);
#pragma unroll
    for (int it = 0; it < 8; it++) {
        int j2 = tid + 256 * it;
        if (2 * j2 < jpad)
            pf2[j2] = __floats2half2_rn(v[it].x * inv, v[it].y * inv);
    }
}

// ---------------- input conversions ----------------
__global__ void __launch_bounds__(256) split_x(const float* __restrict__ x) {
    size_t idx = (size_t)blockIdx.x * 256 + threadIdx.x;
    float v = x[idx];
    __half hi = __float2half_rn(v);
    g_xh[idx] = hi;
    g_xl[idx] = __float2half_rn(v - __half2float(hi));
}

__global__ void __launch_bounds__(256) conv_w(const float* __restrict__ W, int which) {
    size_t idx = (size_t)blockIdx.x * 256 + threadIdx.x;
    g_wf[which][idx] = __float2half_rn(W[idx]);
}

// =================================================================================
// Launch (launch index 5 = scores_tc: profiled by ncu -s 5 -c 1)
// =================================================================================
extern "C" void kernel_launch(void* const* d_in, const int* in_sizes, int n_in,
                              void* d_out, int out_size) {
    (void)in_sizes; (void)n_in; (void)out_size;
    const float* x  = (const float*)d_in[0];
    const float* Wq = (const float*)d_in[1];
    const float* Wk = (const float*)d_in[2];
    const float* Wv = (const float*)d_in[3];
    float* out = (float*)d_out;

    static bool attr_set = false;
    if (!attr_set) {
        cudaFuncSetAttribute(proj_tc,   cudaFuncAttributeMaxDynamicSharedMemorySize, E2_SMEM);
        cudaFuncSetAttribute(scores_tc, cudaFuncAttributeMaxDynamicSharedMemorySize, E1_SMEM);
        cudaFuncSetAttribute(pv_tc,     cudaFuncAttributeMaxDynamicSharedMemorySize, E1_SMEM);
        attr_set = true;
    }

    dim3 pgrid(HID / 128, MTOT / 128);                 // (8, 128)

    split_x<<<(MTOT * HID) / 256, 256>>>(x);           // 0
    conv_w<<<(HID * HID) / 256, 256>>>(Wq, 0);         // 1
    conv_w<<<(HID * HID) / 256, 256>>>(Wk, 1);         // 2
    proj_tc<<<pgrid, 256, E2_SMEM>>>(0);               // 3  -> q
    proj_tc<<<pgrid, 256, E2_SMEM>>>(1);               // 4  -> k
    scores_tc<<<dim3(SLEN / 128, SLEN / 128, BATCH), 256, E1_SMEM>>>();   // 5 (profiled)
    conv_w<<<(HID * HID) / 256, 256>>>(Wv, 2);         // 6
    proj_tc<<<pgrid, 256, E2_SMEM>>>(2);               // 7  -> v^T (fused transpose)
    softmax_kernel<<<MTOT, 256>>>();                   // 8
    pv_tc<<<dim3(HID / 128, SLEN / 128, BATCH), 256, E1_SMEM>>>(out);     // 9
}